// round 3
// baseline (speedup 1.0000x reference)
#include <cuda_runtime.h>

#define D 256
#define NC 64
#define NB 64
#define MAXN 4096
#define SPG 16
#define TILE 32

typedef unsigned long long ull;

#define FMA2(acc, a, b) asm("fma.rn.f32x2 %0, %1, %2, %0;" : "+l"(acc) : "l"(a), "l"(b))
#define ADD2(acc, a)    asm("add.rn.f32x2 %0, %0, %1;"     : "+l"(acc) : "l"(a))
#define DUP(d, x)       asm("mov.b64 %0, {%1, %1};" : "=l"(d) : "r"(__float_as_uint(x)))

__device__ int   g_starts[NB + 1];
__device__ float g_Q[NC * D];
__device__ float g_QtT[D * NC];   // [e][c]
__device__ float g_cK[NC];
__device__ float g_P[NB * NC * D];
__device__ float g_sumA[NB * NC];
__device__ float g_H[NB * NC * D];

// ---------------- meta: detect batch dtype (int32 vs int64) + per-graph starts ----------------
__global__ void k_meta(const void* __restrict__ batch, int n) {
    __shared__ int sh_is32;
    int t = threadIdx.x;
    if (t == 0) {
        long long v = ((const long long*)batch)[n / 4];
        sh_is32 = (v < 0 || v >= NB) ? 1 : 0;
    }
    __syncthreads();
    int is32 = sh_is32;
    int lo = 0, hi = n;
    while (lo < hi) {
        int mid = (lo + hi) >> 1;
        long long bv = is32 ? (long long)((const int*)batch)[mid]
                            : ((const long long*)batch)[mid];
        if (bv < (long long)t) lo = mid + 1; else hi = mid;
    }
    g_starts[t] = lo;
    if (t == 0) g_starts[NB] = n;
}

// ---------------- Q = Qp @ WQ^T + bQ ----------------
__global__ void k_q(const float* __restrict__ Qp, const float* __restrict__ Wq,
                    const float* __restrict__ bq) {
    int c = blockIdx.x, d = threadIdx.x;
    __shared__ float qp[D];
    qp[d] = Qp[c * D + d];
    __syncthreads();
    float a0 = 0.f, a1 = 0.f, a2 = 0.f, a3 = 0.f;
    #pragma unroll 4
    for (int e = 0; e < D; e += 4) {
        a0 = fmaf(qp[e + 0], Wq[d * D + e + 0], a0);
        a1 = fmaf(qp[e + 1], Wq[d * D + e + 1], a1);
        a2 = fmaf(qp[e + 2], Wq[d * D + e + 2], a2);
        a3 = fmaf(qp[e + 3], Wq[d * D + e + 3], a3);
    }
    g_Q[c * D + d] = ((a0 + a1) + (a2 + a3)) + bq[d];
}

// ---------------- Qt[c][e] = sum_d Q[c][d] * WK[d][e]; cK[c] = Q[c]·bK ----------------
__global__ void k_qt(const float* __restrict__ Wk, const float* __restrict__ bk) {
    int c = blockIdx.x, e = threadIdx.x;
    __shared__ float q[D];
    q[e] = g_Q[c * D + e];
    __syncthreads();
    float a0 = 0.f, a1 = 0.f;
    #pragma unroll 4
    for (int d = 0; d < D; d += 2) {
        a0 = fmaf(q[d + 0], Wk[(d + 0) * D + e], a0);
        a1 = fmaf(q[d + 1], Wk[(d + 1) * D + e], a1);
    }
    g_QtT[e * NC + c] = a0 + a1;
    if (e == 0) {
        float ck = 0.f;
        for (int d = 0; d < D; d++) ck += q[d] * bk[d];
        g_cK[c] = ck;
    }
}

// ---------------- main fused kernel ----------------
extern __shared__ float smem[];

__global__ __launch_bounds__(256, 2) void k_main(const float* __restrict__ x,
                                                 float* __restrict__ argout, int has_arg) {
    float* Qt   = smem;                 // D*NC        (65536 B)
    float* Xs   = Qt + D * NC;          // TILE*D      (32768 B)
    float* As   = Xs + TILE * D;        // TILE*NC     (8192 B)
    float* cKs  = As + TILE * NC;       // NC
    float* sAcc = cKs + NC;             // NC

    int t = threadIdx.x;
    int g = blockIdx.x / SPG, sl = blockIdx.x % SPG;
    int s0 = g_starts[g], s1 = g_starts[g + 1];
    int cnt = s1 - s0;
    int chunk = (cnt + SPG - 1) / SPG;
    int i0 = s0 + sl * chunk;
    int i1 = min(i0 + chunk, s1);
    if (i0 >= i1) return;  // uniform across block

    {   // load Qt (coalesced float4)
        const float4* src = (const float4*)g_QtT;
        float4* dst = (float4*)Qt;
        for (int r = t; r < D * NC / 4; r += 256) dst[r] = src[r];
    }
    if (t < NC) { cKs[t] = g_cK[t]; sAcc[t] = 0.f; }

    // Phase-B thread mapping: warp w owns nodes 4w..4w+3; lane owns 1 node x 8 clusters
    const int lane = t & 31;
    const int nB   = (t >> 5) * 4 + (lane >> 3);   // node in tile
    const int jb   = (lane & 7) * 4;               // cluster segment base (second at jb+32)

    // Phase-D thread mapping: 16 consecutive clusters (8 pairs) x 4 dims
    const int cb = t >> 6;          // cluster block: clusters 16cb..16cb+15
    const int db = t & 63;          // dim block: dims 4db..4db+3

    ull P2[8][4];
    #pragma unroll
    for (int p = 0; p < 8; p++)
        #pragma unroll
        for (int dd = 0; dd < 4; dd++) P2[p][dd] = 0ull;
    __syncthreads();

    for (int i = i0; i < i1; i += TILE) {
        int nb = min(TILE, i1 - i);
        {   // load X tile
            const float4* src = (const float4*)(x + (size_t)i * D);
            float4* dst = (float4*)Xs;
            int nt = nb * D / 4;
            for (int r = t; r < nt; r += 256) dst[r] = src[r];
        }
        __syncthreads();

        // ---- Phase B: scores S[n][c] = x_n . Qt_c (all f32x2) ----
        {
            ull s2[4];
            s2[0] = s2[1] = s2[2] = s2[3] = 0ull;
            const float* xsrow = Xs + nB * D;
            #pragma unroll 8
            for (int e = 0; e < D; e += 4) {
                float4 xa = *(const float4*)(xsrow + e);
                float xs4[4] = {xa.x, xa.y, xa.z, xa.w};
                #pragma unroll
                for (int ee = 0; ee < 4; ee++) {
                    ulonglong2 qa = *(const ulonglong2*)(Qt + (e + ee) * NC + jb);
                    ulonglong2 qb = *(const ulonglong2*)(Qt + (e + ee) * NC + 32 + jb);
                    ull xd; DUP(xd, xs4[ee]);
                    FMA2(s2[0], qa.x, xd);
                    FMA2(s2[1], qa.y, xd);
                    FMA2(s2[2], qb.x, xd);
                    FMA2(s2[3], qb.y, xd);
                }
            }
            if (nB < nb) {
                ulonglong2 ca = *(const ulonglong2*)(cKs + jb);
                ulonglong2 cbv = *(const ulonglong2*)(cKs + 32 + jb);
                ADD2(s2[0], ca.x); ADD2(s2[1], ca.y);
                ADD2(s2[2], cbv.x); ADD2(s2[3], cbv.y);
                ull* dst = (ull*)(As + nB * NC + jb);
                dst[0] = s2[0]; dst[1] = s2[1];
                ull* dst2 = (ull*)(As + nB * NC + 32 + jb);
                dst2[0] = s2[2]; dst2[1] = s2[3];
            }
        }
        __syncthreads();

        // ---- Phase C: per-node softmax over 64 clusters + argmax (first-index ties) ----
        {
            int w = t >> 5;
            #pragma unroll
            for (int r = 0; r < TILE / 8; r++) {
                int node = r * 8 + w;
                if (node < nb) {
                    float s0v = As[node * NC + lane], s1v = As[node * NC + lane + 32];
                    float p0 = s0v * 0.0625f, p1 = s1v * 0.0625f;
                    float m = fmaxf(p0, p1);
                    #pragma unroll
                    for (int off = 16; off; off >>= 1)
                        m = fmaxf(m, __shfl_xor_sync(0xffffffffu, m, off));
                    float e0 = expf(p0 - m), e1 = expf(p1 - m);
                    float z = e0 + e1;
                    #pragma unroll
                    for (int off = 16; off; off >>= 1)
                        z += __shfl_xor_sync(0xffffffffu, z, off);
                    float a0 = e0 / z, a1 = e1 / z;
                    float bv; int bi;
                    if (a0 >= a1) { bv = a0; bi = lane; } else { bv = a1; bi = lane + 32; }
                    #pragma unroll
                    for (int off = 16; off; off >>= 1) {
                        float ov = __shfl_xor_sync(0xffffffffu, bv, off);
                        int   oi = __shfl_xor_sync(0xffffffffu, bi, off);
                        if (ov > bv || (ov == bv && oi < bi)) { bv = ov; bi = oi; }
                    }
                    As[node * NC + lane] = a0;
                    As[node * NC + lane + 32] = a1;
                    if (lane == 0 && has_arg) {
                        int pos = (i + node) - s0;
                        argout[(size_t)g * MAXN + pos] = (float)bi;
                    }
                }
            }
        }
        __syncthreads();

        // sumA accumulation (threads < 64)
        if (t < NC) {
            float sa = sAcc[t];
            for (int n = 0; n < nb; n++) sa += As[n * NC + t];
            sAcc[t] = sa;
        }

        // ---- Phase D: P[c][d] += a[c] * x[d] (rank-nb update, all f32x2) ----
        for (int n = 0; n < nb; n++) {
            float4 xv = *(const float4*)(Xs + n * D + 4 * db);
            ull xd0, xd1, xd2, xd3;
            DUP(xd0, xv.x); DUP(xd1, xv.y); DUP(xd2, xv.z); DUP(xd3, xv.w);
            const ulonglong2* a2 = (const ulonglong2*)(As + n * NC + 16 * cb);
            #pragma unroll
            for (int q = 0; q < 4; q++) {
                ulonglong2 av = a2[q];
                FMA2(P2[2 * q][0], av.x, xd0);
                FMA2(P2[2 * q][1], av.x, xd1);
                FMA2(P2[2 * q][2], av.x, xd2);
                FMA2(P2[2 * q][3], av.x, xd3);
                FMA2(P2[2 * q + 1][0], av.y, xd0);
                FMA2(P2[2 * q + 1][1], av.y, xd1);
                FMA2(P2[2 * q + 1][2], av.y, xd2);
                FMA2(P2[2 * q + 1][3], av.y, xd3);
            }
        }
        __syncthreads();
    }

    // flush accumulators: P2[p][dd] holds clusters {16cb+2p, 16cb+2p+1}, dim 4db+dd
    {
        float* pgbase = g_P + (size_t)g * NC * D;
        #pragma unroll
        for (int p = 0; p < 8; p++) {
            int c0 = 16 * cb + 2 * p;
            #pragma unroll
            for (int dd = 0; dd < 4; dd++) {
                int d = 4 * db + dd;
                unsigned int lo = (unsigned int)(P2[p][dd] & 0xffffffffull);
                unsigned int hi = (unsigned int)(P2[p][dd] >> 32);
                atomicAdd(pgbase + (size_t)c0 * D + d,       __uint_as_float(lo));
                atomicAdd(pgbase + (size_t)(c0 + 1) * D + d, __uint_as_float(hi));
            }
        }
    }
    if (t < NC) atomicAdd(&g_sumA[g * NC + t], sAcc[t]);
}

// ---------------- epilogue GEMMs (NT, M=4096, N=256, K=256), f32x2 over k ----------------
template <int MODE>
__global__ __launch_bounds__(256) void k_gemm(const float* __restrict__ Bmat,
                                              const float* __restrict__ bias,
                                              float* __restrict__ Cout) {
    __shared__ float Ash[16 * D];
    int q = threadIdx.x;
    int r0 = blockIdx.x * 16;
    const float* Amat = (MODE == 0) ? g_P : g_H;
    {
        const float4* src = (const float4*)(Amat + (size_t)r0 * D);
        float4* dst = (float4*)Ash;
        for (int r = q; r < 16 * D / 4; r += 256) dst[r] = src[r];
    }
    __syncthreads();
    ull acc2[16];
    #pragma unroll
    for (int rr = 0; rr < 16; rr++) acc2[rr] = 0ull;
    for (int k = 0; k < D; k += 4) {
        ulonglong2 b2 = *(const ulonglong2*)(Bmat + (size_t)q * D + k);
        #pragma unroll
        for (int rr = 0; rr < 16; rr++) {
            ulonglong2 a2 = *(const ulonglong2*)(Ash + rr * D + k);
            FMA2(acc2[rr], a2.x, b2.x);
            FMA2(acc2[rr], a2.y, b2.y);
        }
    }
    #pragma unroll
    for (int rr = 0; rr < 16; rr++) {
        int r = r0 + rr;
        float v = __uint_as_float((unsigned int)(acc2[rr] & 0xffffffffull)) +
                  __uint_as_float((unsigned int)(acc2[rr] >> 32));
        if (MODE == 0) {
            v += g_Q[(r & (NC - 1)) * D + q] + g_sumA[r] * bias[q];
            g_H[(size_t)r * D + q] = v;
        } else {
            v += bias[q];
            Cout[(size_t)r * D + q] = fmaxf(v, 0.f);
        }
    }
}

// ---------------- mask output ----------------
__global__ void k_mask(float* __restrict__ maskout) {
    int idx = blockIdx.x * blockDim.x + threadIdx.x;
    if (idx >= NB * MAXN) return;
    int b = idx >> 12, pos = idx & (MAXN - 1);
    int cnt = g_starts[b + 1] - g_starts[b];
    maskout[idx] = (pos < cnt) ? 1.f : 0.f;
}

extern "C" void kernel_launch(void* const* d_in, const int* in_sizes, int n_in,
                              void* d_out, int out_size) {
    const float* x    = (const float*)d_in[0];
    const void*  bat  = d_in[1];
    const float* Qp   = (const float*)d_in[2];
    const float* WQ_w = (const float*)d_in[3];
    const float* WQ_b = (const float*)d_in[4];
    const float* WK_w = (const float*)d_in[5];
    const float* WK_b = (const float*)d_in[6];
    const float* WV_w = (const float*)d_in[7];
    const float* WV_b = (const float*)d_in[8];
    const float* WO_w = (const float*)d_in[9];
    const float* WO_b = (const float*)d_in[10];
    (void)n_in;

    int n_nodes = in_sizes[0] / D;
    float* out = (float*)d_out;
    int has_arg  = out_size >= (NB * NC * D + NB * MAXN);
    int has_mask = out_size >= (NB * NC * D + 2 * NB * MAXN);
    float* argout  = out + NB * NC * D;
    float* maskout = argout + NB * MAXN;

    void *pP = nullptr, *pS = nullptr;
    cudaGetSymbolAddress(&pP, g_P);
    cudaGetSymbolAddress(&pS, g_sumA);
    cudaMemsetAsync(pP, 0, sizeof(float) * NB * NC * D, 0);
    cudaMemsetAsync(pS, 0, sizeof(float) * NB * NC, 0);
    if (has_arg) cudaMemsetAsync(argout, 0, sizeof(float) * NB * MAXN, 0);

    k_meta<<<1, NB>>>(bat, n_nodes);
    k_q<<<NC, 256>>>(Qp, WQ_w, WQ_b);
    k_qt<<<NC, 256>>>(WK_w, WK_b);

    const int smem_main = (D * NC + TILE * D + TILE * NC + NC + NC) * (int)sizeof(float);
    cudaFuncSetAttribute(k_main, cudaFuncAttributeMaxDynamicSharedMemorySize, smem_main);
    k_main<<<NB * SPG, 256, smem_main>>>(x, argout, has_arg);

    k_gemm<0><<<(NB * NC) / 16, 256>>>(WV_w, WV_b, nullptr);
    k_gemm<1><<<(NB * NC) / 16, 256>>>(WO_w, WO_b, out);

    if (has_mask) k_mask<<<(NB * MAXN) / 256, 256>>>(maskout);
}

// round 4
// speedup vs baseline: 1.7796x; 1.7796x over previous
#include <cuda_runtime.h>

#define D 256
#define NC 64
#define NB 64
#define MAXN 4096
#define SPG 16
#define TILE 64

typedef unsigned long long ull;

#define FMA2(acc, a, b) asm("fma.rn.f32x2 %0, %1, %2, %0;" : "+l"(acc) : "l"(a), "l"(b))
#define ADD2(acc, a)    asm("add.rn.f32x2 %0, %0, %1;"     : "+l"(acc) : "l"(a))
#define DUP(d, x)       asm("mov.b64 %0, {%1, %1};" : "=l"(d) : "r"(__float_as_uint(x)))

__device__ int   g_starts[NB + 1];
__device__ float g_Q[NC * D];
__device__ float g_QtT[D * NC];   // [e][c]
__device__ float g_cK[NC];
__device__ float g_P[NB * NC * D];
__device__ float g_sumA[NB * NC];
__device__ float g_H[NB * NC * D];

// ---------------- meta ----------------
__global__ void k_meta(const void* __restrict__ batch, int n) {
    __shared__ int sh_is32;
    int t = threadIdx.x;
    if (t == 0) {
        long long v = ((const long long*)batch)[n / 4];
        sh_is32 = (v < 0 || v >= NB) ? 1 : 0;
    }
    __syncthreads();
    int is32 = sh_is32;
    int lo = 0, hi = n;
    while (lo < hi) {
        int mid = (lo + hi) >> 1;
        long long bv = is32 ? (long long)((const int*)batch)[mid]
                            : ((const long long*)batch)[mid];
        if (bv < (long long)t) lo = mid + 1; else hi = mid;
    }
    g_starts[t] = lo;
    if (t == 0) g_starts[NB] = n;
}

// ---------------- Q = Qp @ WQ^T + bQ ----------------
__global__ void k_q(const float* __restrict__ Qp, const float* __restrict__ Wq,
                    const float* __restrict__ bq) {
    int c = blockIdx.x, d = threadIdx.x;
    __shared__ float qp[D];
    qp[d] = Qp[c * D + d];
    __syncthreads();
    float a0 = 0.f, a1 = 0.f, a2 = 0.f, a3 = 0.f;
    #pragma unroll 4
    for (int e = 0; e < D; e += 4) {
        a0 = fmaf(qp[e + 0], Wq[d * D + e + 0], a0);
        a1 = fmaf(qp[e + 1], Wq[d * D + e + 1], a1);
        a2 = fmaf(qp[e + 2], Wq[d * D + e + 2], a2);
        a3 = fmaf(qp[e + 3], Wq[d * D + e + 3], a3);
    }
    g_Q[c * D + d] = ((a0 + a1) + (a2 + a3)) + bq[d];
}

// ---------------- Qt[c][e] = sum_d Q[c][d] * WK[d][e]; cK[c] = Q[c]·bK ----------------
__global__ void k_qt(const float* __restrict__ Wk, const float* __restrict__ bk) {
    int c = blockIdx.x, e = threadIdx.x;
    __shared__ float q[D];
    q[e] = g_Q[c * D + e];
    __syncthreads();
    float a0 = 0.f, a1 = 0.f;
    #pragma unroll 4
    for (int d = 0; d < D; d += 2) {
        a0 = fmaf(q[d + 0], Wk[(d + 0) * D + e], a0);
        a1 = fmaf(q[d + 1], Wk[(d + 1) * D + e], a1);
    }
    g_QtT[e * NC + c] = a0 + a1;
    if (e == 0) {
        float ck = 0.f;
        for (int d = 0; d < D; d++) ck += q[d] * bk[d];
        g_cK[c] = ck;
    }
}

// ---------------- main fused kernel ----------------
// smem layout (floats):
//   Qts   [D][NC]          16384   row e: 64 clusters (pairs consumed as ull)
//   Xsw   [TILE][D]        16384   float4-granule swizzled: quad(n,e4) = n*64 + (e4 ^ (n&63))
//   XsT   [D][TILE]        16384   pair-swizzled: off(e,n) = e*64 + 2*((n>>1)^(e&31)) + (n&1)
//   As    [TILE][NC]        4096   pair-swizzled: off(n,c) = n*64 + 2*((c>>1)^(n&31)) + (c&1)
//   cKs   [NC], sAcc [NC]
extern __shared__ float smem[];

__global__ __launch_bounds__(256, 1) void k_main(const float* __restrict__ x,
                                                 float* __restrict__ argout, int has_arg) {
    float* Qts  = smem;
    float* Xsw  = Qts + D * NC;
    float* XsT  = Xsw + TILE * D;
    float* As   = XsT + D * TILE;
    float* cKs  = As + TILE * NC;
    float* sAcc = cKs + NC;

    int t = threadIdx.x;
    int g = blockIdx.x / SPG, sl = blockIdx.x % SPG;
    int s0 = g_starts[g], s1 = g_starts[g + 1];
    int cnt = s1 - s0;
    int chunk = (cnt + SPG - 1) / SPG;
    int i0 = s0 + sl * chunk;
    int i1 = min(i0 + chunk, s1);
    if (i0 >= i1) return;  // uniform across block

    {   // load Qt (coalesced float4)
        const float4* src = (const float4*)g_QtT;
        float4* dst = (float4*)Qts;
        for (int r = t; r < D * NC / 4; r += 256) dst[r] = src[r];
    }
    if (t < NC) { cKs[t] = g_cK[t]; sAcc[t] = 0.f; }

    const int lane = t & 31;
    const int w    = t >> 5;

    // Phase-B mapping: lane owns nodes {2*lane, 2*lane+1}; warp owns clusters 8w..8w+7
    const int cbase = w * 8;

    // Phase-D mapping: clusters 16cb..16cb+15, dims 4db..4db+3
    const int cb = t >> 6;
    const int db = t & 63;

    ull P2[8][4];
    #pragma unroll
    for (int p = 0; p < 8; p++)
        #pragma unroll
        for (int dd = 0; dd < 4; dd++) P2[p][dd] = 0ull;

    // copy-loop constants: thread owns column n_cp, rows e stride 4
    const int n_cp = t & 63;
    const int e_cp0 = t >> 6;
    __syncthreads();

    for (int i = i0; i < i1; i += TILE) {
        int nb = min(TILE, i1 - i);

        // ---- stage: GMEM -> Xsw (swizzled float4, conflict-free STS.128) ----
        for (int r = t; r < nb * (D / 4); r += 256) {
            int n = r >> 6, e4 = r & 63;
            float4 v = *(const float4*)(x + (size_t)(i + n) * D + 4 * e4);
            ((float4*)Xsw)[n * 64 + (e4 ^ n)] = v;   // n < 64 so n&63 == n
        }
        __syncthreads();

        // ---- transpose: Xsw -> XsT (scalar read ~4-way, conflict-free write) ----
        if (n_cp < nb) {
            int nx = n_cp;
            #pragma unroll 4
            for (int e = e_cp0; e < D; e += 4) {
                float v = Xsw[nx * D + 4 * ((e >> 2) ^ nx) + (e & 3)];
                XsT[e * 64 + 2 * ((nx >> 1) ^ (e & 31)) + (nx & 1)] = v;
            }
        }
        __syncthreads();

        // ---- Phase B: S[n][c] = x_n . Qt_c ----
        {
            ull a00 = 0, a01 = 0, a02 = 0, a03 = 0;   // node 2l
            ull a10 = 0, a11 = 0, a12 = 0, a13 = 0;   // node 2l+1
            #pragma unroll 8
            for (int e = 0; e < D; e++) {
                ull x2 = *(const ull*)(XsT + e * 64 + 2 * (lane ^ (e & 31)));
                ull xd0, xd1;
                DUP(xd0, __uint_as_float((unsigned)x2));
                DUP(xd1, __uint_as_float((unsigned)(x2 >> 32)));
                const ull* qt = (const ull*)(Qts + e * NC + cbase);
                ull q0 = qt[0], q1 = qt[1], q2 = qt[2], q3 = qt[3];
                FMA2(a00, q0, xd0); FMA2(a01, q1, xd0);
                FMA2(a02, q2, xd0); FMA2(a03, q3, xd0);
                FMA2(a10, q0, xd1); FMA2(a11, q1, xd1);
                FMA2(a12, q2, xd1); FMA2(a13, q3, xd1);
            }
            const ull* ck = (const ull*)(cKs + cbase);
            ull c0 = ck[0], c1 = ck[1], c2 = ck[2], c3 = ck[3];
            int n0 = 2 * lane, n1 = 2 * lane + 1;
            if (n0 < nb) {
                ADD2(a00, c0); ADD2(a01, c1); ADD2(a02, c2); ADD2(a03, c3);
                int m = n0 & 31;
                *(ull*)(As + n0 * NC + 2 * ((4 * w + 0) ^ m)) = a00;
                *(ull*)(As + n0 * NC + 2 * ((4 * w + 1) ^ m)) = a01;
                *(ull*)(As + n0 * NC + 2 * ((4 * w + 2) ^ m)) = a02;
                *(ull*)(As + n0 * NC + 2 * ((4 * w + 3) ^ m)) = a03;
            }
            if (n1 < nb) {
                ADD2(a10, c0); ADD2(a11, c1); ADD2(a12, c2); ADD2(a13, c3);
                int m = n1 & 31;
                *(ull*)(As + n1 * NC + 2 * ((4 * w + 0) ^ m)) = a10;
                *(ull*)(As + n1 * NC + 2 * ((4 * w + 1) ^ m)) = a11;
                *(ull*)(As + n1 * NC + 2 * ((4 * w + 2) ^ m)) = a12;
                *(ull*)(As + n1 * NC + 2 * ((4 * w + 3) ^ m)) = a13;
            }
        }
        __syncthreads();

        // ---- Phase C: per-node softmax over 64 clusters + argmax (first-index ties) ----
        #pragma unroll
        for (int r = 0; r < TILE / 8; r++) {
            int node = r * 8 + w;
            if (node < nb) {
                int m = node & 31;
                int off0 = node * NC + 2 * ((lane >> 1) ^ m) + (lane & 1);
                int off1 = node * NC + 2 * (((lane >> 1) + 16) ^ m) + (lane & 1);
                float s0v = As[off0], s1v = As[off1];
                float p0 = s0v * 0.0625f, p1 = s1v * 0.0625f;
                float mx = fmaxf(p0, p1);
                #pragma unroll
                for (int off = 16; off; off >>= 1)
                    mx = fmaxf(mx, __shfl_xor_sync(0xffffffffu, mx, off));
                float e0 = expf(p0 - mx), e1 = expf(p1 - mx);
                float z = e0 + e1;
                #pragma unroll
                for (int off = 16; off; off >>= 1)
                    z += __shfl_xor_sync(0xffffffffu, z, off);
                float av0 = e0 / z, av1 = e1 / z;
                float bv; int bi;
                if (av0 >= av1) { bv = av0; bi = lane; } else { bv = av1; bi = lane + 32; }
                #pragma unroll
                for (int off = 16; off; off >>= 1) {
                    float ov = __shfl_xor_sync(0xffffffffu, bv, off);
                    int   oi = __shfl_xor_sync(0xffffffffu, bi, off);
                    if (ov > bv || (ov == bv && oi < bi)) { bv = ov; bi = oi; }
                }
                As[off0] = av0;
                As[off1] = av1;
                if (lane == 0 && has_arg) {
                    int pos = (i + node) - s0;
                    argout[(size_t)g * MAXN + pos] = (float)bi;
                }
            }
        }
        __syncthreads();

        // sumA accumulation (threads < 64), swizzled As read (conflict-free)
        if (t < NC) {
            float sa = sAcc[t];
            int gidx = t >> 1, par = t & 1;
            for (int n = 0; n < nb; n++)
                sa += As[n * NC + 2 * (gidx ^ (n & 31)) + par];
            sAcc[t] = sa;
        }

        // ---- Phase D: P[c][d] += a[c] * x[d] ----
        for (int n = 0; n < nb; n++) {
            int m5 = n & 31;
            float4 xv = ((const float4*)Xsw)[n * 64 + (db ^ n)];
            ull xd0, xd1, xd2, xd3;
            DUP(xd0, xv.x); DUP(xd1, xv.y); DUP(xd2, xv.z); DUP(xd3, xv.w);
            const float* arow = As + n * NC;
            #pragma unroll
            for (int p = 0; p < 8; p++) {
                ull av = *(const ull*)(arow + 2 * ((8 * cb + p) ^ m5));
                FMA2(P2[p][0], av, xd0);
                FMA2(P2[p][1], av, xd1);
                FMA2(P2[p][2], av, xd2);
                FMA2(P2[p][3], av, xd3);
            }
        }
        __syncthreads();
    }

    // flush: P2[p][dd] holds clusters {16cb+2p, 16cb+2p+1}, dim 4db+dd
    {
        float* pgbase = g_P + (size_t)g * NC * D;
        #pragma unroll
        for (int p = 0; p < 8; p++) {
            int c0 = 16 * cb + 2 * p;
            #pragma unroll
            for (int dd = 0; dd < 4; dd++) {
                int d = 4 * db + dd;
                unsigned int lo = (unsigned int)(P2[p][dd] & 0xffffffffull);
                unsigned int hi = (unsigned int)(P2[p][dd] >> 32);
                atomicAdd(pgbase + (size_t)c0 * D + d,       __uint_as_float(lo));
                atomicAdd(pgbase + (size_t)(c0 + 1) * D + d, __uint_as_float(hi));
            }
        }
    }
    if (t < NC) atomicAdd(&g_sumA[g * NC + t], sAcc[t]);
}

// ---------------- epilogue GEMMs (R2-proven form) ----------------
template <int MODE>
__global__ __launch_bounds__(256) void k_gemm(const float* __restrict__ Bmat,
                                              const float* __restrict__ bias,
                                              float* __restrict__ Cout) {
    __shared__ float Ash[16 * D];
    int q = threadIdx.x;
    int r0 = blockIdx.x * 16;
    const float* Amat = (MODE == 0) ? g_P : g_H;
    {
        const float4* src = (const float4*)(Amat + (size_t)r0 * D);
        float4* dst = (float4*)Ash;
        for (int r = q; r < 16 * D / 4; r += 256) dst[r] = src[r];
    }
    __syncthreads();
    float acc[16];
    #pragma unroll
    for (int rr = 0; rr < 16; rr++) acc[rr] = 0.f;
    for (int k = 0; k < D; k += 4) {
        float4 b4 = *(const float4*)(Bmat + (size_t)q * D + k);
        #pragma unroll
        for (int rr = 0; rr < 16; rr++) {
            float4 a4 = *(const float4*)(Ash + rr * D + k);
            acc[rr] = fmaf(a4.x, b4.x, acc[rr]);
            acc[rr] = fmaf(a4.y, b4.y, acc[rr]);
            acc[rr] = fmaf(a4.z, b4.z, acc[rr]);
            acc[rr] = fmaf(a4.w, b4.w, acc[rr]);
        }
    }
    #pragma unroll
    for (int rr = 0; rr < 16; rr++) {
        int r = r0 + rr;
        float v = acc[rr];
        if (MODE == 0) {
            v += g_Q[(r & (NC - 1)) * D + q] + g_sumA[r] * bias[q];
            g_H[(size_t)r * D + q] = v;
        } else {
            v += bias[q];
            Cout[(size_t)r * D + q] = fmaxf(v, 0.f);
        }
    }
}

// ---------------- mask output ----------------
__global__ void k_mask(float* __restrict__ maskout) {
    int idx = blockIdx.x * blockDim.x + threadIdx.x;
    if (idx >= NB * MAXN) return;
    int b = idx >> 12, pos = idx & (MAXN - 1);
    int cnt = g_starts[b + 1] - g_starts[b];
    maskout[idx] = (pos < cnt) ? 1.f : 0.f;
}

extern "C" void kernel_launch(void* const* d_in, const int* in_sizes, int n_in,
                              void* d_out, int out_size) {
    const float* x    = (const float*)d_in[0];
    const void*  bat  = d_in[1];
    const float* Qp   = (const float*)d_in[2];
    const float* WQ_w = (const float*)d_in[3];
    const float* WQ_b = (const float*)d_in[4];
    const float* WK_w = (const float*)d_in[5];
    const float* WK_b = (const float*)d_in[6];
    const float* WV_w = (const float*)d_in[7];
    const float* WV_b = (const float*)d_in[8];
    const float* WO_w = (const float*)d_in[9];
    const float* WO_b = (const float*)d_in[10];
    (void)n_in;

    int n_nodes = in_sizes[0] / D;
    float* out = (float*)d_out;
    int has_arg  = out_size >= (NB * NC * D + NB * MAXN);
    int has_mask = out_size >= (NB * NC * D + 2 * NB * MAXN);
    float* argout  = out + NB * NC * D;
    float* maskout = argout + NB * MAXN;

    void *pP = nullptr, *pS = nullptr;
    cudaGetSymbolAddress(&pP, g_P);
    cudaGetSymbolAddress(&pS, g_sumA);
    cudaMemsetAsync(pP, 0, sizeof(float) * NB * NC * D, 0);
    cudaMemsetAsync(pS, 0, sizeof(float) * NB * NC, 0);
    if (has_arg) cudaMemsetAsync(argout, 0, sizeof(float) * NB * MAXN, 0);

    k_meta<<<1, NB>>>(bat, n_nodes);
    k_q<<<NC, 256>>>(Qp, WQ_w, WQ_b);
    k_qt<<<NC, 256>>>(WK_w, WK_b);

    const int smem_main = (D * NC + TILE * D + D * TILE + TILE * NC + NC + NC) * (int)sizeof(float);
    cudaFuncSetAttribute(k_main, cudaFuncAttributeMaxDynamicSharedMemorySize, smem_main);
    k_main<<<NB * SPG, 256, smem_main>>>(x, argout, has_arg);

    k_gemm<0><<<(NB * NC) / 16, 256>>>(WV_w, WV_b, nullptr);
    k_gemm<1><<<(NB * NC) / 16, 256>>>(WO_w, WO_b, out);

    if (has_mask) k_mask<<<(NB * MAXN) / 256, 256>>>(maskout);
}

// round 5
// speedup vs baseline: 1.7898x; 1.0057x over previous
#include <cuda_runtime.h>

#define D 256
#define NC 64
#define NB 64
#define MAXN 4096
#define SPG 16
#define TILE 64
#define NT 512

typedef unsigned long long ull;

#define FMA2(acc, a, b) asm("fma.rn.f32x2 %0, %1, %2, %0;" : "+l"(acc) : "l"(a), "l"(b))
#define ADD2(acc, a)    asm("add.rn.f32x2 %0, %0, %1;"     : "+l"(acc) : "l"(a))
#define DUP(d, x)       asm("mov.b64 %0, {%1, %1};" : "=l"(d) : "r"(__float_as_uint(x)))

__device__ int   g_starts[NB + 1];
__device__ float g_Q[NC * D];
__device__ float g_QtT[D * NC];   // [e][c]
__device__ float g_cK[NC];
__device__ float g_P[NB * NC * D];
__device__ float g_sumA[NB * NC];
__device__ float g_H[NB * NC * D];

// ---------------- meta ----------------
__global__ void k_meta(const void* __restrict__ batch, int n) {
    __shared__ int sh_is32;
    int t = threadIdx.x;
    if (t == 0) {
        long long v = ((const long long*)batch)[n / 4];
        sh_is32 = (v < 0 || v >= NB) ? 1 : 0;
    }
    __syncthreads();
    int is32 = sh_is32;
    int lo = 0, hi = n;
    while (lo < hi) {
        int mid = (lo + hi) >> 1;
        long long bv = is32 ? (long long)((const int*)batch)[mid]
                            : ((const long long*)batch)[mid];
        if (bv < (long long)t) lo = mid + 1; else hi = mid;
    }
    g_starts[t] = lo;
    if (t == 0) g_starts[NB] = n;
}

// ---------------- Q = Qp @ WQ^T + bQ ----------------
__global__ void k_q(const float* __restrict__ Qp, const float* __restrict__ Wq,
                    const float* __restrict__ bq) {
    int c = blockIdx.x, d = threadIdx.x;
    __shared__ float qp[D];
    qp[d] = Qp[c * D + d];
    __syncthreads();
    float a0 = 0.f, a1 = 0.f, a2 = 0.f, a3 = 0.f;
    #pragma unroll 4
    for (int e = 0; e < D; e += 4) {
        a0 = fmaf(qp[e + 0], Wq[d * D + e + 0], a0);
        a1 = fmaf(qp[e + 1], Wq[d * D + e + 1], a1);
        a2 = fmaf(qp[e + 2], Wq[d * D + e + 2], a2);
        a3 = fmaf(qp[e + 3], Wq[d * D + e + 3], a3);
    }
    g_Q[c * D + d] = ((a0 + a1) + (a2 + a3)) + bq[d];
}

// ---------------- Qt[c][e] = sum_d Q[c][d] * WK[d][e]; cK[c] = Q[c]·bK ----------------
__global__ void k_qt(const float* __restrict__ Wk, const float* __restrict__ bk) {
    int c = blockIdx.x, e = threadIdx.x;
    __shared__ float q[D];
    q[e] = g_Q[c * D + e];
    __syncthreads();
    float a0 = 0.f, a1 = 0.f;
    #pragma unroll 4
    for (int d = 0; d < D; d += 2) {
        a0 = fmaf(q[d + 0], Wk[(d + 0) * D + e], a0);
        a1 = fmaf(q[d + 1], Wk[(d + 1) * D + e], a1);
    }
    g_QtT[e * NC + c] = a0 + a1;
    if (e == 0) {
        float ck = 0.f;
        for (int d = 0; d < D; d++) ck += q[d] * bk[d];
        g_cK[c] = ck;
    }
}

// ---------------- main fused kernel (512 threads) ----------------
// smem layout (floats):
//   Qts [D][NC] 16384 | Xsw [TILE][D] 16384 (float4-swizzled: quad(n,e4)=n*64+(e4^n))
//   XsT [D][TILE] 16384 (pair-swizzled: off(e,n)=e*64+2*((n>>1)^(e&31))+(n&1))
//   As  [TILE][NC] 4096 (pair-swizzled: off(n,c)=n*64+2*((c>>1)^(n&31))+(c&1))
//   cKs [NC], sAcc [NC]
extern __shared__ float smem[];

__global__ __launch_bounds__(NT, 1) void k_main(const float* __restrict__ x,
                                                float* __restrict__ argout, int has_arg) {
    float* Qts  = smem;
    float* Xsw  = Qts + D * NC;
    float* XsT  = Xsw + TILE * D;
    float* As   = XsT + D * TILE;
    float* cKs  = As + TILE * NC;
    float* sAcc = cKs + NC;

    int t = threadIdx.x;
    int g = blockIdx.x / SPG, sl = blockIdx.x % SPG;
    int s0 = g_starts[g], s1 = g_starts[g + 1];
    int cnt = s1 - s0;
    int chunk = (cnt + SPG - 1) / SPG;
    int i0 = s0 + sl * chunk;
    int i1 = min(i0 + chunk, s1);
    if (i0 >= i1) return;  // uniform across block

    {   // load Qt (coalesced float4)
        const float4* src = (const float4*)g_QtT;
        float4* dst = (float4*)Qts;
        for (int r = t; r < D * NC / 4; r += NT) dst[r] = src[r];
    }
    if (t < NC) { cKs[t] = g_cK[t]; sAcc[t] = 0.f; }

    const int lane = t & 31;
    const int w    = t >> 5;            // 0..15

    // Phase-B mapping: lane owns nodes {2l, 2l+1}; warp owns clusters 4w..4w+3
    const int cbase = w * 4;

    // Phase-D mapping: clusters 8cb..8cb+7, dims 4db..4db+3
    const int cb = t >> 6;              // 0..7
    const int db = t & 63;

    ull P2[4][4];
    #pragma unroll
    for (int p = 0; p < 4; p++)
        #pragma unroll
        for (int dd = 0; dd < 4; dd++) P2[p][dd] = 0ull;

    const int n_cp = t & 63;
    const int e_cp0 = t >> 6;           // 0..7
    __syncthreads();

    for (int i = i0; i < i1; i += TILE) {
        int nb = min(TILE, i1 - i);

        // ---- stage: GMEM -> Xsw (swizzled float4, conflict-free STS.128) ----
        for (int r = t; r < nb * (D / 4); r += NT) {
            int n = r >> 6, e4 = r & 63;
            float4 v = *(const float4*)(x + (size_t)(i + n) * D + 4 * e4);
            ((float4*)Xsw)[n * 64 + (e4 ^ n)] = v;
        }
        __syncthreads();

        // ---- transpose: Xsw -> XsT (read ~4-way, write conflict-free) ----
        if (n_cp < nb) {
            int nx = n_cp;
            #pragma unroll 4
            for (int e = e_cp0; e < D; e += 8) {
                float v = Xsw[nx * D + 4 * ((e >> 2) ^ nx) + (e & 3)];
                XsT[e * 64 + 2 * ((nx >> 1) ^ (e & 31)) + (nx & 1)] = v;
            }
        }
        __syncthreads();

        // ---- Phase B: S[n][c] = x_n . Qt_c ----
        {
            ull a0 = 0, a1 = 0;   // node 2l,  cluster pairs {4w,4w+1},{4w+2,4w+3}
            ull b0 = 0, b1 = 0;   // node 2l+1
            #pragma unroll 8
            for (int e = 0; e < D; e++) {
                ull x2 = *(const ull*)(XsT + e * 64 + 2 * (lane ^ (e & 31)));
                ull xd0, xd1;
                DUP(xd0, __uint_as_float((unsigned)x2));
                DUP(xd1, __uint_as_float((unsigned)(x2 >> 32)));
                const ull* qt = (const ull*)(Qts + e * NC + cbase);
                ull q0 = qt[0], q1 = qt[1];
                FMA2(a0, q0, xd0); FMA2(a1, q1, xd0);
                FMA2(b0, q0, xd1); FMA2(b1, q1, xd1);
            }
            const ull* ck = (const ull*)(cKs + cbase);
            ull c0 = ck[0], c1 = ck[1];
            int n0 = 2 * lane, n1 = 2 * lane + 1;
            if (n0 < nb) {
                ADD2(a0, c0); ADD2(a1, c1);
                int m = n0 & 31;
                *(ull*)(As + n0 * NC + 2 * ((2 * w + 0) ^ m)) = a0;
                *(ull*)(As + n0 * NC + 2 * ((2 * w + 1) ^ m)) = a1;
            }
            if (n1 < nb) {
                ADD2(b0, c0); ADD2(b1, c1);
                int m = n1 & 31;
                *(ull*)(As + n1 * NC + 2 * ((2 * w + 0) ^ m)) = b0;
                *(ull*)(As + n1 * NC + 2 * ((2 * w + 1) ^ m)) = b1;
            }
        }
        __syncthreads();

        // ---- Phase C: softmax over 64 clusters + argmax (first-index ties) ----
        #pragma unroll
        for (int r = 0; r < TILE / 16; r++) {
            int node = r * 16 + w;
            if (node < nb) {
                int m = node & 31;
                int off0 = node * NC + 2 * ((lane >> 1) ^ m) + (lane & 1);
                int off1 = node * NC + 2 * (((lane >> 1) + 16) ^ m) + (lane & 1);
                float s0v = As[off0], s1v = As[off1];
                float p0 = s0v * 0.0625f, p1 = s1v * 0.0625f;
                float mx = fmaxf(p0, p1);
                #pragma unroll
                for (int off = 16; off; off >>= 1)
                    mx = fmaxf(mx, __shfl_xor_sync(0xffffffffu, mx, off));
                float e0 = expf(p0 - mx), e1 = expf(p1 - mx);
                float z = e0 + e1;
                #pragma unroll
                for (int off = 16; off; off >>= 1)
                    z += __shfl_xor_sync(0xffffffffu, z, off);
                float av0 = e0 / z, av1 = e1 / z;
                float bv; int bi;
                if (av0 >= av1) { bv = av0; bi = lane; } else { bv = av1; bi = lane + 32; }
                #pragma unroll
                for (int off = 16; off; off >>= 1) {
                    float ov = __shfl_xor_sync(0xffffffffu, bv, off);
                    int   oi = __shfl_xor_sync(0xffffffffu, bi, off);
                    if (ov > bv || (ov == bv && oi < bi)) { bv = ov; bi = oi; }
                }
                As[off0] = av0;
                As[off1] = av1;
                if (lane == 0 && has_arg) {
                    int pos = (i + node) - s0;
                    argout[(size_t)g * MAXN + pos] = (float)bi;
                }
            }
        }
        __syncthreads();

        // sumA accumulation (threads < 64)
        if (t < NC) {
            float sa = sAcc[t];
            int gidx = t >> 1, par = t & 1;
            for (int n = 0; n < nb; n++)
                sa += As[n * NC + 2 * (gidx ^ (n & 31)) + par];
            sAcc[t] = sa;
        }

        // ---- Phase D: P[c][d] += a[c] * x[d] ----
        for (int n = 0; n < nb; n++) {
            int m5 = n & 31;
            float4 xv = ((const float4*)Xsw)[n * 64 + (db ^ n)];
            ull xd0, xd1, xd2, xd3;
            DUP(xd0, xv.x); DUP(xd1, xv.y); DUP(xd2, xv.z); DUP(xd3, xv.w);
            const float* arow = As + n * NC;
            #pragma unroll
            for (int p = 0; p < 4; p++) {
                ull av = *(const ull*)(arow + 2 * ((4 * cb + p) ^ m5));
                FMA2(P2[p][0], av, xd0);
                FMA2(P2[p][1], av, xd1);
                FMA2(P2[p][2], av, xd2);
                FMA2(P2[p][3], av, xd3);
            }
        }
        __syncthreads();
    }

    // flush: P2[p][dd] holds clusters {8cb+2p, 8cb+2p+1}, dim 4db+dd
    {
        float* pgbase = g_P + (size_t)g * NC * D;
        #pragma unroll
        for (int p = 0; p < 4; p++) {
            int c0 = 8 * cb + 2 * p;
            #pragma unroll
            for (int dd = 0; dd < 4; dd++) {
                int d = 4 * db + dd;
                unsigned int lo = (unsigned int)(P2[p][dd] & 0xffffffffull);
                unsigned int hi = (unsigned int)(P2[p][dd] >> 32);
                atomicAdd(pgbase + (size_t)c0 * D + d,       __uint_as_float(lo));
                atomicAdd(pgbase + (size_t)(c0 + 1) * D + d, __uint_as_float(hi));
            }
        }
    }
    if (t < NC) atomicAdd(&g_sumA[g * NC + t], sAcc[t]);
}

// ---------------- epilogue GEMMs ----------------
template <int MODE>
__global__ __launch_bounds__(256) void k_gemm(const float* __restrict__ Bmat,
                                              const float* __restrict__ bias,
                                              float* __restrict__ Cout) {
    __shared__ float Ash[16 * D];
    int q = threadIdx.x;
    int r0 = blockIdx.x * 16;
    const float* Amat = (MODE == 0) ? g_P : g_H;
    {
        const float4* src = (const float4*)(Amat + (size_t)r0 * D);
        float4* dst = (float4*)Ash;
        for (int r = q; r < 16 * D / 4; r += 256) dst[r] = src[r];
    }
    __syncthreads();
    float acc[16];
    #pragma unroll
    for (int rr = 0; rr < 16; rr++) acc[rr] = 0.f;
    for (int k = 0; k < D; k += 4) {
        float4 b4 = *(const float4*)(Bmat + (size_t)q * D + k);
        #pragma unroll
        for (int rr = 0; rr < 16; rr++) {
            float4 a4 = *(const float4*)(Ash + rr * D + k);
            acc[rr] = fmaf(a4.x, b4.x, acc[rr]);
            acc[rr] = fmaf(a4.y, b4.y, acc[rr]);
            acc[rr] = fmaf(a4.z, b4.z, acc[rr]);
            acc[rr] = fmaf(a4.w, b4.w, acc[rr]);
        }
    }
    #pragma unroll
    for (int rr = 0; rr < 16; rr++) {
        int r = r0 + rr;
        float v = acc[rr];
        if (MODE == 0) {
            v += g_Q[(r & (NC - 1)) * D + q] + g_sumA[r] * bias[q];
            g_H[(size_t)r * D + q] = v;
        } else {
            v += bias[q];
            Cout[(size_t)r * D + q] = fmaxf(v, 0.f);
        }
    }
}

// ---------------- mask output ----------------
__global__ void k_mask(float* __restrict__ maskout) {
    int idx = blockIdx.x * blockDim.x + threadIdx.x;
    if (idx >= NB * MAXN) return;
    int b = idx >> 12, pos = idx & (MAXN - 1);
    int cnt = g_starts[b + 1] - g_starts[b];
    maskout[idx] = (pos < cnt) ? 1.f : 0.f;
}

extern "C" void kernel_launch(void* const* d_in, const int* in_sizes, int n_in,
                              void* d_out, int out_size) {
    const float* x    = (const float*)d_in[0];
    const void*  bat  = d_in[1];
    const float* Qp   = (const float*)d_in[2];
    const float* WQ_w = (const float*)d_in[3];
    const float* WQ_b = (const float*)d_in[4];
    const float* WK_w = (const float*)d_in[5];
    const float* WK_b = (const float*)d_in[6];
    const float* WV_w = (const float*)d_in[7];
    const float* WV_b = (const float*)d_in[8];
    const float* WO_w = (const float*)d_in[9];
    const float* WO_b = (const float*)d_in[10];
    (void)n_in;

    int n_nodes = in_sizes[0] / D;
    float* out = (float*)d_out;
    int has_arg  = out_size >= (NB * NC * D + NB * MAXN);
    int has_mask = out_size >= (NB * NC * D + 2 * NB * MAXN);
    float* argout  = out + NB * NC * D;
    float* maskout = argout + NB * MAXN;

    void *pP = nullptr, *pS = nullptr;
    cudaGetSymbolAddress(&pP, g_P);
    cudaGetSymbolAddress(&pS, g_sumA);
    cudaMemsetAsync(pP, 0, sizeof(float) * NB * NC * D, 0);
    cudaMemsetAsync(pS, 0, sizeof(float) * NB * NC, 0);
    if (has_arg) cudaMemsetAsync(argout, 0, sizeof(float) * NB * MAXN, 0);

    k_meta<<<1, NB>>>(bat, n_nodes);
    k_q<<<NC, 256>>>(Qp, WQ_w, WQ_b);
    k_qt<<<NC, 256>>>(WK_w, WK_b);

    const int smem_main = (D * NC + TILE * D + D * TILE + TILE * NC + NC + NC) * (int)sizeof(float);
    cudaFuncSetAttribute(k_main, cudaFuncAttributeMaxDynamicSharedMemorySize, smem_main);
    k_main<<<NB * SPG, NT, smem_main>>>(x, argout, has_arg);

    k_gemm<0><<<(NB * NC) / 16, 256>>>(WV_w, WV_b, nullptr);
    k_gemm<1><<<(NB * NC) / 16, 256>>>(WO_w, WO_b, out);

    if (has_mask) k_mask<<<(NB * MAXN) / 256, 256>>>(maskout);
}

// round 8
// speedup vs baseline: 1.9941x; 1.1141x over previous
#include <cuda_runtime.h>
#include <cuda_bf16.h>

#define D 256
#define NC 64
#define NB 64
#define MAXN 4096
#define SPG 16
#define TILE 64
#define NT 512

typedef unsigned long long ull;
typedef unsigned int u32;

#define FMA2(acc, a, b) asm("fma.rn.f32x2 %0, %1, %2, %0;" : "+l"(acc) : "l"(a), "l"(b))
#define ADD2(acc, a)    asm("add.rn.f32x2 %0, %0, %1;"     : "+l"(acc) : "l"(a))
#define DUP(d, x)       asm("mov.b64 %0, {%1, %1};" : "=l"(d) : "r"(__float_as_uint(x)))
#define CVTBF2(r, lo, hi) asm("cvt.rn.bf16x2.f32 %0, %1, %2;" : "=r"(r) : "f"(hi), "f"(lo))
#define SWZ(off) ((off) ^ (((off) >> 3) & 0x70))

#define LDSM4(r0, r1, r2, r3, addr) \
    asm volatile("ldmatrix.sync.aligned.m8n8.x4.shared.b16 {%0,%1,%2,%3}, [%4];" \
                 : "=r"(r0), "=r"(r1), "=r"(r2), "=r"(r3) : "r"(addr))

#define MMA16816(c, a0, a1, a2, a3, b0, b1) \
    asm volatile("mma.sync.aligned.m16n8k16.row.col.f32.bf16.bf16.f32 " \
                 "{%0,%1,%2,%3}, {%4,%5,%6,%7}, {%8,%9}, {%0,%1,%2,%3};" \
                 : "+f"((c)[0]), "+f"((c)[1]), "+f"((c)[2]), "+f"((c)[3]) \
                 : "r"(a0), "r"(a1), "r"(a2), "r"(a3), "r"(b0), "r"(b1))

__device__ int   g_starts[NB + 1];
__device__ float g_Q[NC * D];
__device__ float g_QtT[D * NC];   // [e][c]
__device__ float g_cK[NC];
__device__ float g_P[NB * NC * D];
__device__ float g_sumA[NB * NC];
__device__ float g_H[NB * NC * D];

__device__ __forceinline__ u32 s2u(const void* p) {
    u32 a;
    asm("{ .reg .u64 t; cvta.to.shared.u64 t, %1; cvt.u32.u64 %0, t; }" : "=r"(a) : "l"(p));
    return a;
}

// split v0,v1 -> packed bf16x2 hi and lo parts
__device__ __forceinline__ void split2(float v0, float v1, u32& hi, u32& lo) {
    CVTBF2(hi, v0, v1);
    float h0 = __uint_as_float(hi << 16);
    float h1 = __uint_as_float(hi & 0xffff0000u);
    CVTBF2(lo, v0 - h0, v1 - h1);
}

// ---------------- meta ----------------
__global__ void k_meta(const void* __restrict__ batch, int n) {
    __shared__ int sh_is32;
    int t = threadIdx.x;
    if (t == 0) {
        long long v = ((const long long*)batch)[n / 4];
        sh_is32 = (v < 0 || v >= NB) ? 1 : 0;
    }
    __syncthreads();
    int is32 = sh_is32;
    int lo = 0, hi = n;
    while (lo < hi) {
        int mid = (lo + hi) >> 1;
        long long bv = is32 ? (long long)((const int*)batch)[mid]
                            : ((const long long*)batch)[mid];
        if (bv < (long long)t) lo = mid + 1; else hi = mid;
    }
    g_starts[t] = lo;
    if (t == 0) g_starts[NB] = n;
}

// ---------------- Q = Qp @ WQ^T + bQ ----------------
__global__ void k_q(const float* __restrict__ Qp, const float* __restrict__ Wq,
                    const float* __restrict__ bq) {
    int c = blockIdx.x, d = threadIdx.x;
    __shared__ float qp[D];
    qp[d] = Qp[c * D + d];
    __syncthreads();
    float a0 = 0.f, a1 = 0.f, a2 = 0.f, a3 = 0.f;
    #pragma unroll 4
    for (int e = 0; e < D; e += 4) {
        a0 = fmaf(qp[e + 0], Wq[d * D + e + 0], a0);
        a1 = fmaf(qp[e + 1], Wq[d * D + e + 1], a1);
        a2 = fmaf(qp[e + 2], Wq[d * D + e + 2], a2);
        a3 = fmaf(qp[e + 3], Wq[d * D + e + 3], a3);
    }
    g_Q[c * D + d] = ((a0 + a1) + (a2 + a3)) + bq[d];
}

// ---------------- Qt[c][e] = sum_d Q[c][d]*WK[d][e]; cK[c] = Q[c]·bK ----------------
__global__ void k_qt(const float* __restrict__ Wk, const float* __restrict__ bk) {
    int c = blockIdx.x, e = threadIdx.x;
    __shared__ float q[D];
    q[e] = g_Q[c * D + e];
    __syncthreads();
    float a0 = 0.f, a1 = 0.f;
    #pragma unroll 4
    for (int d = 0; d < D; d += 2) {
        a0 = fmaf(q[d + 0], Wk[(d + 0) * D + e], a0);
        a1 = fmaf(q[d + 1], Wk[(d + 1) * D + e], a1);
    }
    g_QtT[e * NC + c] = a0 + a1;
    if (e == 0) {
        float ck = 0.f;
        for (int d = 0; d < D; d++) ck += q[d] * bk[d];
        g_cK[c] = ck;
    }
}

// ---------------- main fused kernel ----------------
// smem float offsets:
//   Qts    [0, 16384)       f32 [e][c]
//   XsT    [16384, 32768)   f32 pair-swizzled [e][n]
//   As     [32768, 36864)   f32 pair-swizzled [n][c]
//   Xst2 / XbfH union [36864, 45056)  staging 32KB / bf16-hi [256][64] SWZ rows 128B
//   XbfL   [45056, 53248)   bf16-lo [256][64]
//   AbfH   [53248, 55296)   bf16-hi [64][64]
//   AbfL   [55296, 57344)   bf16-lo [64][64]
//   cKs 57344, sAcc 57408
#define SMEM_FLOATS 57472
extern __shared__ float smem[];

__global__ __launch_bounds__(NT, 1) void k_main(const float* __restrict__ x,
                                                float* __restrict__ argout, int has_arg) {
    float* Qts  = smem;
    float* XsT  = smem + 16384;
    float* As   = smem + 32768;
    float* Xst2 = smem + 36864;
    float* cKs  = smem + 57344;
    float* sAcc = smem + 57408;

    int t = threadIdx.x;
    int g = blockIdx.x / SPG, sl = blockIdx.x % SPG;
    int s0 = g_starts[g], s1 = g_starts[g + 1];
    int cnt = s1 - s0;
    int chunk = (cnt + SPG - 1) / SPG;
    int i0 = s0 + sl * chunk;
    int i1 = min(i0 + chunk, s1);
    if (i0 >= i1) return;  // uniform across block

    u32 sb = s2u(smem);
    u32 xbfH = sb + 36864 * 4;
    u32 xbfL = sb + 45056 * 4;
    u32 abfH = sb + 53248 * 4;
    u32 abfL = sb + 55296 * 4;

    {   // load Qt (coalesced float4)
        const float4* src = (const float4*)g_QtT;
        float4* dst = (float4*)Qts;
        for (int r = t; r < D * NC / 4; r += NT) dst[r] = src[r];
    }
    if (t < NC) { cKs[t] = g_cK[t]; sAcc[t] = 0.f; }
    for (int r = t; r < 16384; r += NT) XsT[r] = 0.f;  // keep padded lanes finite

    const int lane = t & 31;
    const int w    = t >> 5;            // 0..15
    const int cbase = w * 4;            // Phase-B clusters

    // MMA warp mapping
    const int wr = w & 3;               // cluster row block (x16)
    const int wc = w >> 2;              // dim col block (x64)
    const int a_row = 16 * wr + (lane & 7) + 8 * ((lane >> 3) & 1);
    const int a_hi = lane >> 4;
    const int a_sw = a_row & 7;
    const int b_rofs = (lane & 7) + 8 * ((lane >> 4) & 1);
    const int b_kc = (lane >> 3) & 1;

    float acc[8][4];
    #pragma unroll
    for (int nj = 0; nj < 8; nj++)
        #pragma unroll
        for (int q = 0; q < 4; q++) acc[nj][q] = 0.f;

    __syncthreads();

    for (int i = i0; i < i1; i += TILE) {
        int nb = min(TILE, i1 - i);

        // ---- stage + transpose in 32-node halves ----
        for (int h = 0; h < 2; h++) {
            int base = 32 * h, nbh = nb - base;
            if (nbh <= 0) break;
            if (nbh > 32) nbh = 32;
            for (int r = t; r < nbh * 64; r += NT) {
                int n = r >> 6, e4 = r & 63;
                float4 v = *(const float4*)(x + (size_t)(i + base + n) * D + 4 * e4);
                ((float4*)Xst2)[n * 64 + (e4 ^ n)] = v;
            }
            __syncthreads();
            {
                int nl = t & 31, e0 = t >> 5;
                if (nl < nbh) {
                    int n = base + nl;
                    #pragma unroll 4
                    for (int e = e0; e < D; e += 16) {
                        float v = Xst2[nl * D + 4 * ((e >> 2) ^ nl) + (e & 3)];
                        XsT[e * 64 + 2 * ((n >> 1) ^ (e & 31)) + (n & 1)] = v;
                    }
                }
            }
            __syncthreads();
        }

        // ---- Phase B: S[n][c] = x_n . Qt_c (exact f32, f32x2) ----
        {
            ull a0 = 0, a1 = 0;   // node 2*lane
            ull b0 = 0, b1 = 0;   // node 2*lane+1
            #pragma unroll 8
            for (int e = 0; e < D; e++) {
                ull x2 = *(const ull*)(XsT + e * 64 + 2 * (lane ^ (e & 31)));
                ull xd0, xd1;
                DUP(xd0, __uint_as_float((unsigned)x2));
                DUP(xd1, __uint_as_float((unsigned)(x2 >> 32)));
                const ull* qt = (const ull*)(Qts + e * NC + cbase);
                ull q0 = qt[0], q1 = qt[1];
                FMA2(a0, q0, xd0); FMA2(a1, q1, xd0);
                FMA2(b0, q0, xd1); FMA2(b1, q1, xd1);
            }
            const ull* ck = (const ull*)(cKs + cbase);
            ull c0 = ck[0], c1 = ck[1];
            int n0 = 2 * lane, n1 = 2 * lane + 1;
            if (n0 < nb) {
                ADD2(a0, c0); ADD2(a1, c1);
                int m = n0 & 31;
                *(ull*)(As + n0 * NC + 2 * ((2 * w + 0) ^ m)) = a0;
                *(ull*)(As + n0 * NC + 2 * ((2 * w + 1) ^ m)) = a1;
            }
            if (n1 < nb) {
                ADD2(b0, c0); ADD2(b1, c1);
                int m = n1 & 31;
                *(ull*)(As + n1 * NC + 2 * ((2 * w + 0) ^ m)) = b0;
                *(ull*)(As + n1 * NC + 2 * ((2 * w + 1) ^ m)) = b1;
            }
        }
        __syncthreads();

        // ---- Phase C: softmax over 64 clusters + argmax (first-index ties) ----
        #pragma unroll
        for (int r = 0; r < TILE / 16; r++) {
            int node = r * 16 + w;
            if (node < nb) {
                int m = node & 31;
                int off0 = node * NC + 2 * ((lane >> 1) ^ m) + (lane & 1);
                int off1 = node * NC + 2 * (((lane >> 1) + 16) ^ m) + (lane & 1);
                float s0v = As[off0], s1v = As[off1];
                float p0 = s0v * 0.0625f, p1 = s1v * 0.0625f;
                float mx = fmaxf(p0, p1);
                #pragma unroll
                for (int off = 16; off; off >>= 1)
                    mx = fmaxf(mx, __shfl_xor_sync(0xffffffffu, mx, off));
                float e0 = expf(p0 - mx), e1 = expf(p1 - mx);
                float z = e0 + e1;
                #pragma unroll
                for (int off = 16; off; off >>= 1)
                    z += __shfl_xor_sync(0xffffffffu, z, off);
                float av0 = e0 / z, av1 = e1 / z;
                float bv; int bi;
                if (av0 >= av1) { bv = av0; bi = lane; } else { bv = av1; bi = lane + 32; }
                #pragma unroll
                for (int off = 16; off; off >>= 1) {
                    float ov = __shfl_xor_sync(0xffffffffu, bv, off);
                    int   oi = __shfl_xor_sync(0xffffffffu, bi, off);
                    if (ov > bv || (ov == bv && oi < bi)) { bv = ov; bi = oi; }
                }
                As[off0] = av0;
                As[off1] = av1;
                if (lane == 0 && has_arg) {
                    int pos = (i + node) - s0;
                    argout[(size_t)g * MAXN + pos] = (float)bi;
                }
            }
        }
        __syncthreads();

        // sumA accumulation (exact f32, threads < 64)
        if (t < NC) {
            float sa = sAcc[t];
            int gidx = t >> 1, par = t & 1;
            for (int n = 0; n < nb; n++)
                sa += As[n * NC + 2 * (gidx ^ (n & 31)) + par];
            sAcc[t] = sa;
        }

        // ---- convert A -> AbfH/AbfL (bf16 hi/lo, [c][n] swizzled 128B rows) ----
        {
            int c = t >> 3, n0 = (t & 7) * 8;
            u32 ph[4], pl[4];
            #pragma unroll
            for (int q = 0; q < 4; q++) {
                int na = n0 + 2 * q, nb2 = na + 1;
                float va = (na < nb)  ? As[na * NC + 2 * ((c >> 1) ^ (na & 31)) + (c & 1)] : 0.f;
                float vb = (nb2 < nb) ? As[nb2 * NC + 2 * ((c >> 1) ^ (nb2 & 31)) + (c & 1)] : 0.f;
                split2(va, vb, ph[q], pl[q]);
            }
            u32 so = SWZ(c * 128 + n0 * 2);
            *(uint4*)((char*)smem + (abfH - sb) + so) = make_uint4(ph[0], ph[1], ph[2], ph[3]);
            *(uint4*)((char*)smem + (abfL - sb) + so) = make_uint4(pl[0], pl[1], pl[2], pl[3]);
        }
        // ---- convert X^T -> XbfH/XbfL (bf16 hi/lo, [d][n]; XbfH overwrites staging) ----
        {
            int e = t >> 1, h = t & 1;
            #pragma unroll
            for (int k4 = 0; k4 < 4; k4++) {
                u32 ph[4], pl[4];
                #pragma unroll
                for (int m2 = 0; m2 < 4; m2++) {
                    int l = 16 * h + 4 * k4 + m2;  // node-pair index
                    ull xv = *(const ull*)(XsT + e * 64 + 2 * (l ^ (e & 31)));
                    float lo = __uint_as_float((u32)xv);
                    float hi = __uint_as_float((u32)(xv >> 32));
                    split2(lo, hi, ph[m2], pl[m2]);
                }
                u32 so = SWZ(e * 128 + (32 * h + 8 * k4) * 2);
                *(uint4*)((char*)smem + (xbfH - sb) + so) = make_uint4(ph[0], ph[1], ph[2], ph[3]);
                *(uint4*)((char*)smem + (xbfL - sb) + so) = make_uint4(pl[0], pl[1], pl[2], pl[3]);
            }
        }
        __syncthreads();

        // ---- Phase D (tensor pipe): acc += Ah*Xh^T + Al*Xh^T + Ah*Xl^T ----
        #pragma unroll
        for (int ks = 0; ks < 4; ks++) {
            u32 a_off = (a_row << 7) + (((2 * ks + a_hi) ^ a_sw) << 4);
            u32 ah0, ah1, ah2, ah3, al0, al1, al2, al3;
            LDSM4(ah0, ah1, ah2, ah3, abfH + a_off);
            LDSM4(al0, al1, al2, al3, abfL + a_off);
            #pragma unroll
            for (int jj = 0; jj < 4; jj++) {
                int jrow = 64 * wc + 16 * jj + b_rofs;
                u32 b_off = (jrow << 7) + (((2 * ks + b_kc) ^ (jrow & 7)) << 4);
                u32 bh0, bh1, bh2, bh3, bl0, bl1, bl2, bl3;
                LDSM4(bh0, bh1, bh2, bh3, xbfH + b_off);
                LDSM4(bl0, bl1, bl2, bl3, xbfL + b_off);
                MMA16816(acc[2 * jj],     ah0, ah1, ah2, ah3, bh0, bh1);
                MMA16816(acc[2 * jj],     al0, al1, al2, al3, bh0, bh1);
                MMA16816(acc[2 * jj],     ah0, ah1, ah2, ah3, bl0, bl1);
                MMA16816(acc[2 * jj + 1], ah0, ah1, ah2, ah3, bh2, bh3);
                MMA16816(acc[2 * jj + 1], al0, al1, al2, al3, bh2, bh3);
                MMA16816(acc[2 * jj + 1], ah0, ah1, ah2, ah3, bl2, bl3);
            }
        }
        __syncthreads();
    }

    // ---- flush accumulators ----
    {
        float* pgb = g_P + (size_t)g * NC * D;
        int r0 = 16 * wr + (lane >> 2);
        #pragma unroll
        for (int nj = 0; nj < 8; nj++) {
            int col = 64 * wc + 8 * nj + 2 * (lane & 3);
            atomicAdd(pgb + (size_t)r0 * D + col,           acc[nj][0]);
            atomicAdd(pgb + (size_t)r0 * D + col + 1,       acc[nj][1]);
            atomicAdd(pgb + (size_t)(r0 + 8) * D + col,     acc[nj][2]);
            atomicAdd(pgb + (size_t)(r0 + 8) * D + col + 1, acc[nj][3]);
        }
    }
    if (t < NC) atomicAdd(&g_sumA[g * NC + t], sAcc[t]);
}

// ---------------- epilogue GEMMs (32 rows/block) ----------------
template <int MODE>
__global__ __launch_bounds__(256) void k_gemm(const float* __restrict__ Bmat,
                                              const float* __restrict__ bias,
                                              float* __restrict__ Cout) {
    __shared__ float Ash[32 * D];
    int q = threadIdx.x;
    int r0 = blockIdx.x * 32;
    const float* Amat = (MODE == 0) ? g_P : g_H;
    {
        const float4* src = (const float4*)(Amat + (size_t)r0 * D);
        float4* dst = (float4*)Ash;
        for (int r = q; r < 32 * D / 4; r += 256) dst[r] = src[r];
    }
    __syncthreads();
    float acc[32];
    #pragma unroll
    for (int rr = 0; rr < 32; rr++) acc[rr] = 0.f;
    for (int k = 0; k < D; k += 4) {
        float4 b4 = *(const float4*)(Bmat + (size_t)q * D + k);
        #pragma unroll
        for (int rr = 0; rr < 32; rr++) {
            float4 a4 = *(const float4*)(Ash + rr * D + k);
            acc[rr] = fmaf(a4.x, b4.x, acc[rr]);
            acc[rr] = fmaf(a4.y, b4.y, acc[rr]);
            acc[rr] = fmaf(a4.z, b4.z, acc[rr]);
            acc[rr] = fmaf(a4.w, b4.w, acc[rr]);
        }
    }
    #pragma unroll
    for (int rr = 0; rr < 32; rr++) {
        int r = r0 + rr;
        float v = acc[rr];
        if (MODE == 0) {
            v += g_Q[(r & (NC - 1)) * D + q] + g_sumA[r] * bias[q];
            g_H[(size_t)r * D + q] = v;
        } else {
            v += bias[q];
            Cout[(size_t)r * D + q] = fmaxf(v, 0.f);
        }
    }
}

// ---------------- mask output ----------------
__global__ void k_mask(float* __restrict__ maskout) {
    int idx = blockIdx.x * blockDim.x + threadIdx.x;
    if (idx >= NB * MAXN) return;
    int b = idx >> 12, pos = idx & (MAXN - 1);
    int cnt = g_starts[b + 1] - g_starts[b];
    maskout[idx] = (pos < cnt) ? 1.f : 0.f;
}

extern "C" void kernel_launch(void* const* d_in, const int* in_sizes, int n_in,
                              void* d_out, int out_size) {
    const float* x    = (const float*)d_in[0];
    const void*  bat  = d_in[1];
    const float* Qp   = (const float*)d_in[2];
    const float* WQ_w = (const float*)d_in[3];
    const float* WQ_b = (const float*)d_in[4];
    const float* WK_w = (const float*)d_in[5];
    const float* WK_b = (const float*)d_in[6];
    const float* WV_w = (const float*)d_in[7];
    const float* WV_b = (const float*)d_in[8];
    const float* WO_w = (const float*)d_in[9];
    const float* WO_b = (const float*)d_in[10];
    (void)n_in;

    int n_nodes = in_sizes[0] / D;
    float* out = (float*)d_out;
    int has_arg  = out_size >= (NB * NC * D + NB * MAXN);
    int has_mask = out_size >= (NB * NC * D + 2 * NB * MAXN);
    float* argout  = out + NB * NC * D;
    float* maskout = argout + NB * MAXN;

    void *pP = nullptr, *pS = nullptr;
    cudaGetSymbolAddress(&pP, g_P);
    cudaGetSymbolAddress(&pS, g_sumA);
    cudaMemsetAsync(pP, 0, sizeof(float) * NB * NC * D, 0);
    cudaMemsetAsync(pS, 0, sizeof(float) * NB * NC, 0);
    if (has_arg) cudaMemsetAsync(argout, 0, sizeof(float) * NB * MAXN, 0);

    k_meta<<<1, NB>>>(bat, n_nodes);
    k_q<<<NC, 256>>>(Qp, WQ_w, WQ_b);
    k_qt<<<NC, 256>>>(WK_w, WK_b);

    const int smem_main = SMEM_FLOATS * (int)sizeof(float);
    cudaFuncSetAttribute(k_main, cudaFuncAttributeMaxDynamicSharedMemorySize, smem_main);
    k_main<<<NB * SPG, NT, smem_main>>>(x, argout, has_arg);

    k_gemm<0><<<(NB * NC) / 32, 256>>>(WV_w, WV_b, nullptr);
    k_gemm<1><<<(NB * NC) / 32, 256>>>(WO_w, WO_b, out);

    if (has_mask) k_mask<<<(NB * MAXN) / 256, 256>>>(maskout);
}

// round 9
// speedup vs baseline: 2.5413x; 1.2744x over previous
#include <cuda_runtime.h>
#include <cuda_bf16.h>

#define D 256
#define NC 64
#define NB 64
#define MAXN 4096
#define SPG 16
#define TILE 64
#define NT 512
#define FLAG_EPS 3e-6f

typedef unsigned long long ull;
typedef unsigned int u32;

#define CVTBF2(r, lo, hi) asm("cvt.rn.bf16x2.f32 %0, %1, %2;" : "=r"(r) : "f"(hi), "f"(lo))

#define LDSM4(r0, r1, r2, r3, addr) \
    asm volatile("ldmatrix.sync.aligned.m8n8.x4.shared.b16 {%0,%1,%2,%3}, [%4];" \
                 : "=r"(r0), "=r"(r1), "=r"(r2), "=r"(r3) : "r"(addr))

#define LDSM4T(r0, r1, r2, r3, addr) \
    asm volatile("ldmatrix.sync.aligned.m8n8.x4.trans.shared.b16 {%0,%1,%2,%3}, [%4];" \
                 : "=r"(r0), "=r"(r1), "=r"(r2), "=r"(r3) : "r"(addr))

#define MMA16816(c, a0, a1, a2, a3, b0, b1) \
    asm volatile("mma.sync.aligned.m16n8k16.row.col.f32.bf16.bf16.f32 " \
                 "{%0,%1,%2,%3}, {%4,%5,%6,%7}, {%8,%9}, {%0,%1,%2,%3};" \
                 : "+f"((c)[0]), "+f"((c)[1]), "+f"((c)[2]), "+f"((c)[3]) \
                 : "r"(a0), "r"(a1), "r"(a2), "r"(a3), "r"(b0), "r"(b1))

__device__ int   g_starts[NB + 1];
__device__ float g_Q[NC * D];
__device__ float g_QtT[D * NC];   // [e][c] (fallback)
__device__ float g_QtC[NC * D];   // [c][e] (bf16 conversion source)
__device__ float g_cK[NC];
__device__ float g_P[NB * NC * D];
__device__ float g_sumA[NB * NC];
__device__ float g_H[NB * NC * D];

__device__ __forceinline__ u32 s2u(const void* p) {
    u32 a;
    asm("{ .reg .u64 t; cvta.to.shared.u64 t, %1; cvt.u32.u64 %0, t; }" : "=r"(a) : "l"(p));
    return a;
}

__device__ __forceinline__ void split2(float v0, float v1, u32& hi, u32& lo) {
    CVTBF2(hi, v0, v1);
    float h0 = __uint_as_float(hi << 16);
    float h1 = __uint_as_float(hi & 0xffff0000u);
    CVTBF2(lo, v0 - h0, v1 - h1);
}

// ---------------- meta ----------------
__global__ void k_meta(const void* __restrict__ batch, int n) {
    __shared__ int sh_is32;
    int t = threadIdx.x;
    if (t == 0) {
        long long v = ((const long long*)batch)[n / 4];
        sh_is32 = (v < 0 || v >= NB) ? 1 : 0;
    }
    __syncthreads();
    int is32 = sh_is32;
    int lo = 0, hi = n;
    while (lo < hi) {
        int mid = (lo + hi) >> 1;
        long long bv = is32 ? (long long)((const int*)batch)[mid]
                            : ((const long long*)batch)[mid];
        if (bv < (long long)t) lo = mid + 1; else hi = mid;
    }
    g_starts[t] = lo;
    if (t == 0) g_starts[NB] = n;
}

// ---------------- Q = Qp @ WQ^T + bQ ----------------
__global__ void k_q(const float* __restrict__ Qp, const float* __restrict__ Wq,
                    const float* __restrict__ bq) {
    int c = blockIdx.x, d = threadIdx.x;
    __shared__ float qp[D];
    qp[d] = Qp[c * D + d];
    __syncthreads();
    float a0 = 0.f, a1 = 0.f, a2 = 0.f, a3 = 0.f;
    #pragma unroll 4
    for (int e = 0; e < D; e += 4) {
        a0 = fmaf(qp[e + 0], Wq[d * D + e + 0], a0);
        a1 = fmaf(qp[e + 1], Wq[d * D + e + 1], a1);
        a2 = fmaf(qp[e + 2], Wq[d * D + e + 2], a2);
        a3 = fmaf(qp[e + 3], Wq[d * D + e + 3], a3);
    }
    g_Q[c * D + d] = ((a0 + a1) + (a2 + a3)) + bq[d];
}

// ---------------- Qt[c][e]; cK[c] ----------------
__global__ void k_qt(const float* __restrict__ Wk, const float* __restrict__ bk) {
    int c = blockIdx.x, e = threadIdx.x;
    __shared__ float q[D];
    q[e] = g_Q[c * D + e];
    __syncthreads();
    float a0 = 0.f, a1 = 0.f;
    #pragma unroll 4
    for (int d = 0; d < D; d += 2) {
        a0 = fmaf(q[d + 0], Wk[(d + 0) * D + e], a0);
        a1 = fmaf(q[d + 1], Wk[(d + 1) * D + e], a1);
    }
    float v = a0 + a1;
    g_QtT[e * NC + c] = v;
    g_QtC[c * D + e] = v;
    if (e == 0) {
        float ck = 0.f;
        for (int d = 0; d < D; d++) ck += q[d] * bk[d];
        g_cK[c] = ck;
    }
}

// ---------------- main fused kernel ----------------
// smem floats:
//   XnbfH [0,8192)      bf16-hi x [64n][256e], rows 512B, swz off^( (n&7)<<4 )
//   XnbfL [8192,16384)
//   QtbfH [16384,24576) bf16-hi Qt [64c][256e], rows 512B
//   QtbfL [24576,32768)
//   As    [32768,36864) f32 pair-swizzled [n][c]: n*64 + 2*((c>>1)^(n&31)) + (c&1)
//   AbfH  [36864,38912) bf16-hi A [64c][64n], rows 128B, SW128
//   AbfL  [38912,40960)
//   cKs 40960, sAcc 41024, flags 41088 (int cnt + 64 entries)
#define SMEM_FLOATS 41216
extern __shared__ float smem[];

__global__ __launch_bounds__(NT, 1) void k_main(const float* __restrict__ x,
                                                float* __restrict__ argout, int has_arg) {
    float* As   = smem + 32768;
    float* cKs  = smem + 40960;
    float* sAcc = smem + 41024;
    int*   flagn = (int*)(smem + 41088);
    int*   flagl = (int*)(smem + 41089);

    int t = threadIdx.x;
    int g = blockIdx.x / SPG, sl = blockIdx.x % SPG;
    int s0 = g_starts[g], s1 = g_starts[g + 1];
    int cnt = s1 - s0;
    int chunk = (cnt + SPG - 1) / SPG;
    int i0 = s0 + sl * chunk;
    int i1 = min(i0 + chunk, s1);
    if (i0 >= i1) return;  // uniform across block

    u32 sb = s2u(smem);
    const u32 xnH = sb, xnL = sb + 32768;
    const u32 qtH = sb + 65536, qtL = sb + 98304;
    const u32 abH = sb + 147456, abL = sb + 155648;

    // init: zero Xnbf, load cK, convert Qt -> split bf16 [c][e]
    for (int r = t; r < 16384; r += NT) ((u32*)smem)[r] = 0u;
    if (t < NC) { cKs[t] = g_cK[t]; sAcc[t] = 0.f; }
    if (t == 0) *flagn = 0;
    for (int r = t; r < NC * (D / 4); r += NT) {
        int c = r >> 6, e4 = r & 63;
        float4 v = *(const float4*)(g_QtC + c * D + 4 * e4);
        u32 h0, l0, h1, l1;
        split2(v.x, v.y, h0, l0);
        split2(v.z, v.w, h1, l1);
        u32 off = c * 512 + ((e4 * 8) ^ ((c & 7) << 4));
        *(uint2*)((char*)smem + (qtH - sb) + off) = make_uint2(h0, h1);
        *(uint2*)((char*)smem + (qtL - sb) + off) = make_uint2(l0, l1);
    }

    const int lane = t & 31;
    const int w    = t >> 5;            // 0..15

    // Phase-B MMA mapping: cw = c-block(16), nw = n-block(16)
    const int cw = w & 3, nw = w >> 2;
    const int pb_arow = 16 * cw + (lane & 7) + 8 * ((lane >> 3) & 1);
    const int pb_ae   = (lane >> 4) & 1;
    const int pb_asw  = (pb_arow & 7) << 4;
    const int pb_brow = 16 * nw + (lane & 7) + 8 * ((lane >> 4) & 1);
    const int pb_be   = (lane >> 3) & 1;
    const int pb_bsw  = (pb_brow & 7) << 4;
    // writeout indices
    const int wo_c = 16 * cw + (lane >> 2);
    const int wo_n = 16 * nw + 2 * (lane & 3);

    // Phase-D mapping (as R8): wr = c-block(16), wc = d-block(64)
    const int wr = w & 3, wc = w >> 2;
    const int a_row = 16 * wr + (lane & 7) + 8 * ((lane >> 3) & 1);
    const int a_hi = lane >> 4;
    const int a_sw = a_row & 7;
    const int pd_ksub = (lane & 7) + 8 * ((lane >> 3) & 1);
    const int pd_dh = (lane >> 4) & 1;

    float acc[8][4];
    #pragma unroll
    for (int nj = 0; nj < 8; nj++)
        #pragma unroll
        for (int q = 0; q < 4; q++) acc[nj][q] = 0.f;

    __syncthreads();

    for (int i = i0; i < i1; i += TILE) {
        int nb = min(TILE, i1 - i);

        // ---- stage: x -> split bf16 Xnbf [n][e] ----
        if (t == 0) *flagn = 0;
        for (int r = t; r < nb * 64; r += NT) {
            int n = r >> 6, e4 = r & 63;
            float4 v = *(const float4*)(x + (size_t)(i + n) * D + 4 * e4);
            u32 h0, l0, h1, l1;
            split2(v.x, v.y, h0, l0);
            split2(v.z, v.w, h1, l1);
            u32 off = n * 512 + ((e4 * 8) ^ ((n & 7) << 4));
            *(uint2*)((char*)smem + off)         = make_uint2(h0, h1);
            *(uint2*)((char*)smem + 32768 + off) = make_uint2(l0, l1);
        }
        __syncthreads();

        // ---- Phase B (tensor): S[16c x 16n] per warp, k = 256 ----
        {
            float sc[2][4];
            #pragma unroll
            for (int h = 0; h < 2; h++)
                #pragma unroll
                for (int q = 0; q < 4; q++) sc[h][q] = 0.f;
            #pragma unroll
            for (int ks = 0; ks < 16; ks++) {
                u32 aoff = pb_arow * 512 + ((32 * ks + 16 * pb_ae) ^ pb_asw);
                u32 boff = pb_brow * 512 + ((32 * ks + 16 * pb_be) ^ pb_bsw);
                u32 ah0, ah1, ah2, ah3, al0, al1, al2, al3;
                u32 bh0, bh1, bh2, bh3, bl0, bl1, bl2, bl3;
                LDSM4(ah0, ah1, ah2, ah3, qtH + aoff);
                LDSM4(al0, al1, al2, al3, qtL + aoff);
                LDSM4(bh0, bh1, bh2, bh3, xnH + boff);
                LDSM4(bl0, bl1, bl2, bl3, xnL + boff);
                MMA16816(sc[0], ah0, ah1, ah2, ah3, bh0, bh1);
                MMA16816(sc[0], al0, al1, al2, al3, bh0, bh1);
                MMA16816(sc[0], ah0, ah1, ah2, ah3, bl0, bl1);
                MMA16816(sc[1], ah0, ah1, ah2, ah3, bh2, bh3);
                MMA16816(sc[1], al0, al1, al2, al3, bh2, bh3);
                MMA16816(sc[1], ah0, ah1, ah2, ah3, bl2, bl3);
            }
            // write S + cK to As (pair-swizzled)
            float ck0 = cKs[wo_c], ck1 = cKs[wo_c + 8];
            #pragma unroll
            for (int h = 0; h < 2; h++) {
                int n0 = wo_n + 8 * h;
                int m0 = n0 & 31, m1 = (n0 + 1) & 31;
                As[n0 * 64 + 2 * ((wo_c >> 1) ^ m0) + (wo_c & 1)] = sc[h][0] + ck0;
                As[(n0 + 1) * 64 + 2 * ((wo_c >> 1) ^ m1) + (wo_c & 1)] = sc[h][1] + ck0;
                int c1 = wo_c + 8;
                As[n0 * 64 + 2 * ((c1 >> 1) ^ m0) + (c1 & 1)] = sc[h][2] + ck1;
                As[(n0 + 1) * 64 + 2 * ((c1 >> 1) ^ m1) + (c1 & 1)] = sc[h][3] + ck1;
            }
        }
        __syncthreads();

        // ---- Phase C: softmax + argmax + near-tie flagging ----
        #pragma unroll
        for (int r = 0; r < TILE / 16; r++) {
            int node = r * 16 + w;
            if (node < nb) {
                int m = node & 31;
                int off0 = node * NC + 2 * ((lane >> 1) ^ m) + (lane & 1);
                int off1 = node * NC + 2 * (((lane >> 1) + 16) ^ m) + (lane & 1);
                float s0v = As[off0], s1v = As[off1];
                float p0 = s0v * 0.0625f, p1 = s1v * 0.0625f;
                float mx = fmaxf(p0, p1);
                #pragma unroll
                for (int off = 16; off; off >>= 1)
                    mx = fmaxf(mx, __shfl_xor_sync(0xffffffffu, mx, off));
                float e0 = expf(p0 - mx), e1 = expf(p1 - mx);
                float z = e0 + e1;
                #pragma unroll
                for (int off = 16; off; off >>= 1)
                    z += __shfl_xor_sync(0xffffffffu, z, off);
                float av0 = e0 / z, av1 = e1 / z;
                float bv; int bi;
                if (av0 >= av1) { bv = av0; bi = lane; } else { bv = av1; bi = lane + 32; }
                #pragma unroll
                for (int off = 16; off; off >>= 1) {
                    float ov = __shfl_xor_sync(0xffffffffu, bv, off);
                    int   oi = __shfl_xor_sync(0xffffffffu, bi, off);
                    if (ov > bv || (ov == bv && oi < bi)) { bv = ov; bi = oi; }
                }
                As[off0] = av0;
                As[off1] = av1;
                // second best (excluding winner)
                float x0 = (bi == lane) ? -1e30f : av0;
                float x1 = (bi == lane + 32) ? -1e30f : av1;
                float m2 = fmaxf(x0, x1);
                #pragma unroll
                for (int off = 16; off; off >>= 1)
                    m2 = fmaxf(m2, __shfl_xor_sync(0xffffffffu, m2, off));
                if (lane == 0) {
                    if (has_arg) {
                        int pos = (i + node) - s0;
                        argout[(size_t)g * MAXN + pos] = (float)bi;
                    }
                    if (bv - m2 < FLAG_EPS) {
                        int k = atomicAdd(flagn, 1);
                        flagl[k] = node;
                    }
                }
            }
        }
        __syncthreads();

        // ---- fallback: exact argmax for flagged nodes (rare) ----
        int nf = *flagn;
        if (has_arg) {
            for (int f = w; f < nf; f += 16) {
                int node = flagl[f];
                const float* xr = x + (size_t)(i + node) * D;
                float s0 = 0.f, s1 = 0.f;
                for (int e = 0; e < D; e++) {
                    float xe = __ldg(xr + e);
                    float2 q = *(const float2*)(g_QtT + e * NC + 2 * lane);
                    s0 = fmaf(xe, q.x, s0);
                    s1 = fmaf(xe, q.y, s1);
                }
                s0 += cKs[2 * lane];
                s1 += cKs[2 * lane + 1];
                float p0 = s0 * 0.0625f, p1 = s1 * 0.0625f;
                float mx = fmaxf(p0, p1);
                #pragma unroll
                for (int off = 16; off; off >>= 1)
                    mx = fmaxf(mx, __shfl_xor_sync(0xffffffffu, mx, off));
                float e0 = expf(p0 - mx), e1 = expf(p1 - mx);
                float z = e0 + e1;
                #pragma unroll
                for (int off = 16; off; off >>= 1)
                    z += __shfl_xor_sync(0xffffffffu, z, off);
                float av0 = e0 / z, av1 = e1 / z;
                float bv; int bi;
                if (av0 >= av1) { bv = av0; bi = 2 * lane; } else { bv = av1; bi = 2 * lane + 1; }
                #pragma unroll
                for (int off = 16; off; off >>= 1) {
                    float ov = __shfl_xor_sync(0xffffffffu, bv, off);
                    int   oi = __shfl_xor_sync(0xffffffffu, bi, off);
                    if (ov > bv || (ov == bv && oi < bi)) { bv = ov; bi = oi; }
                }
                if (lane == 0) {
                    int pos = (i + node) - s0;  // careful: s0 reused name? shadows float!
                    argout[(size_t)g * MAXN + ((i + node) - g_starts[g] - (i0 - i0))] = (float)bi;
                    (void)pos;
                }
            }
        }

        // sumA accumulation (threads < 64)
        if (t < NC) {
            float sa = sAcc[t];
            int gidx = t >> 1, par = t & 1;
            for (int n = 0; n < nb; n++)
                sa += As[n * NC + 2 * (gidx ^ (n & 31)) + par];
            sAcc[t] = sa;
        }

        // ---- convert A -> AbfH/AbfL ([c][n], rows 128B SW128) ----
        {
            int c = t >> 3, n0 = (t & 7) * 8;
            u32 ph[4], pl[4];
            #pragma unroll
            for (int q = 0; q < 4; q++) {
                int na = n0 + 2 * q, nb2 = na + 1;
                float va = (na < nb)  ? As[na * NC + 2 * ((c >> 1) ^ (na & 31)) + (c & 1)] : 0.f;
                float vb = (nb2 < nb) ? As[nb2 * NC + 2 * ((c >> 1) ^ (nb2 & 31)) + (c & 1)] : 0.f;
                split2(va, vb, ph[q], pl[q]);
            }
            u32 so = (c * 128 + n0 * 2);
            so = so ^ ((so >> 3) & 0x70);
            *(uint4*)((char*)smem + (abH - sb) + so) = make_uint4(ph[0], ph[1], ph[2], ph[3]);
            *(uint4*)((char*)smem + (abL - sb) + so) = make_uint4(pl[0], pl[1], pl[2], pl[3]);
        }
        __syncthreads();

        // ---- Phase D (tensor): acc += A[c][n] * X[n][d] via ldmatrix.trans ----
        #pragma unroll
        for (int ks = 0; ks < 4; ks++) {
            u32 a_off = (a_row << 7) + (((2 * ks + a_hi) ^ a_sw) << 4);
            u32 ah0, ah1, ah2, ah3, al0, al1, al2, al3;
            LDSM4(ah0, ah1, ah2, ah3, abH + a_off);
            LDSM4(al0, al1, al2, al3, abL + a_off);
            int k_row = 16 * ks + pd_ksub;
            u32 bbase = k_row * 512;
            u32 bsw = (k_row & 7) << 4;
            #pragma unroll
            for (int jj = 0; jj < 4; jj++) {
                u32 b_off = bbase + ((128 * wc + 32 * jj + 16 * pd_dh) ^ bsw);
                u32 bh0, bh1, bh2, bh3, bl0, bl1, bl2, bl3;
                LDSM4T(bh0, bh1, bh2, bh3, xnH + b_off);
                LDSM4T(bl0, bl1, bl2, bl3, xnL + b_off);
                MMA16816(acc[2 * jj],     ah0, ah1, ah2, ah3, bh0, bh1);
                MMA16816(acc[2 * jj],     al0, al1, al2, al3, bh0, bh1);
                MMA16816(acc[2 * jj],     ah0, ah1, ah2, ah3, bl0, bl1);
                MMA16816(acc[2 * jj + 1], ah0, ah1, ah2, ah3, bh2, bh3);
                MMA16816(acc[2 * jj + 1], al0, al1, al2, al3, bh2, bh3);
                MMA16816(acc[2 * jj + 1], ah0, ah1, ah2, ah3, bl2, bl3);
            }
        }
        __syncthreads();
    }

    // ---- flush accumulators ----
    {
        float* pgb = g_P + (size_t)g * NC * D;
        int r0 = 16 * wr + (lane >> 2);
        #pragma unroll
        for (int nj = 0; nj < 8; nj++) {
            int col = 64 * wc + 8 * nj + 2 * (lane & 3);
            atomicAdd(pgb + (size_t)r0 * D + col,           acc[nj][0]);
            atomicAdd(pgb + (size_t)r0 * D + col + 1,       acc[nj][1]);
            atomicAdd(pgb + (size_t)(r0 + 8) * D + col,     acc[nj][2]);
            atomicAdd(pgb + (size_t)(r0 + 8) * D + col + 1, acc[nj][3]);
        }
    }
    if (t < NC) atomicAdd(&g_sumA[g * NC + t], sAcc[t]);
}

// ---------------- epilogue GEMMs (32 rows/block) ----------------
template <int MODE>
__global__ __launch_bounds__(256) void k_gemm(const float* __restrict__ Bmat,
                                              const float* __restrict__ bias,
                                              float* __restrict__ Cout) {
    __shared__ float Ash[32 * D];
    int q = threadIdx.x;
    int r0 = blockIdx.x * 32;
    const float* Amat = (MODE == 0) ? g_P : g_H;
    {
        const float4* src = (const float4*)(Amat + (size_t)r0 * D);
        float4* dst = (float4*)Ash;
        for (int r = q; r < 32 * D / 4; r += 256) dst[r] = src[r];
    }
    __syncthreads();
    float acc[32];
    #pragma unroll
    for (int rr = 0; rr < 32; rr++) acc[rr] = 0.f;
    for (int k = 0; k < D; k += 4) {
        float4 b4 = *(const float4*)(Bmat + (size_t)q * D + k);
        #pragma unroll
        for (int rr = 0; rr < 32; rr++) {
            float4 a4 = *(const float4*)(Ash + rr * D + k);
            acc[rr] = fmaf(a4.x, b4.x, acc[rr]);
            acc[rr] = fmaf(a4.y, b4.y, acc[rr]);
            acc[rr] = fmaf(a4.z, b4.z, acc[rr]);
            acc[rr] = fmaf(a4.w, b4.w, acc[rr]);
        }
    }
    #pragma unroll
    for (int rr = 0; rr < 32; rr++) {
        int r = r0 + rr;
        float v = acc[rr];
        if (MODE == 0) {
            v += g_Q[(r & (NC - 1)) * D + q] + g_sumA[r] * bias[q];
            g_H[(size_t)r * D + q] = v;
        } else {
            v += bias[q];
            Cout[(size_t)r * D + q] = fmaxf(v, 0.f);
        }
    }
}

// ---------------- mask output ----------------
__global__ void k_mask(float* __restrict__ maskout) {
    int idx = blockIdx.x * blockDim.x + threadIdx.x;
    if (idx >= NB * MAXN) return;
    int b = idx >> 12, pos = idx & (MAXN - 1);
    int cnt = g_starts[b + 1] - g_starts[b];
    maskout[idx] = (pos < cnt) ? 1.f : 0.f;
}

extern "C" void kernel_launch(void* const* d_in, const int* in_sizes, int n_in,
                              void* d_out, int out_size) {
    const float* x    = (const float*)d_in[0];
    const void*  bat  = d_in[1];
    const float* Qp   = (const float*)d_in[2];
    const float* WQ_w = (const float*)d_in[3];
    const float* WQ_b = (const float*)d_in[4];
    const float* WK_w = (const float*)d_in[5];
    const float* WK_b = (const float*)d_in[6];
    const float* WV_w = (const float*)d_in[7];
    const float* WV_b = (const float*)d_in[8];
    const float* WO_w = (const float*)d_in[9];
    const float* WO_b = (const float*)d_in[10];
    (void)n_in;

    int n_nodes = in_sizes[0] / D;
    float* out = (float*)d_out;
    int has_arg  = out_size >= (NB * NC * D + NB * MAXN);
    int has_mask = out_size >= (NB * NC * D + 2 * NB * MAXN);
    float* argout  = out + NB * NC * D;
    float* maskout = argout + NB * MAXN;

    void *pP = nullptr, *pS = nullptr;
    cudaGetSymbolAddress(&pP, g_P);
    cudaGetSymbolAddress(&pS, g_sumA);
    cudaMemsetAsync(pP, 0, sizeof(float) * NB * NC * D, 0);
    cudaMemsetAsync(pS, 0, sizeof(float) * NB * NC, 0);
    if (has_arg) cudaMemsetAsync(argout, 0, sizeof(float) * NB * MAXN, 0);

    k_meta<<<1, NB>>>(bat, n_nodes);
    k_q<<<NC, 256>>>(Qp, WQ_w, WQ_b);
    k_qt<<<NC, 256>>>(WK_w, WK_b);

    const int smem_main = SMEM_FLOATS * (int)sizeof(float);
    cudaFuncSetAttribute(k_main, cudaFuncAttributeMaxDynamicSharedMemorySize, smem_main);
    k_main<<<NB * SPG, NT, smem_main>>>(x, argout, has_arg);

    k_gemm<0><<<(NB * NC) / 32, 256>>>(WV_w, WV_b, nullptr);
    k_gemm<1><<<(NB * NC) / 32, 256>>>(WO_w, WO_b, out);

    if (has_mask) k_mask<<<(NB * MAXN) / 256, 256>>>(maskout);
}

// round 10
// speedup vs baseline: 2.6178x; 1.0301x over previous
#include <cuda_runtime.h>
#include <cuda_bf16.h>

#define D 256
#define NC 64
#define NB 64
#define MAXN 4096
#define SPG 16
#define TILE 64
#define NT 512
#define FLAG_EPS 3e-6f

typedef unsigned long long ull;
typedef unsigned int u32;

#define FMA2(acc, a, b) asm("fma.rn.f32x2 %0, %1, %2, %0;" : "+l"(acc) : "l"(a), "l"(b))
#define DUP(d, x)       asm("mov.b64 %0, {%1, %1};" : "=l"(d) : "r"(__float_as_uint(x)))
#define CVTBF2(r, lo, hi) asm("cvt.rn.bf16x2.f32 %0, %1, %2;" : "=r"(r) : "f"(hi), "f"(lo))

#define LDSM4(r0, r1, r2, r3, addr) \
    asm volatile("ldmatrix.sync.aligned.m8n8.x4.shared.b16 {%0,%1,%2,%3}, [%4];" \
                 : "=r"(r0), "=r"(r1), "=r"(r2), "=r"(r3) : "r"(addr))

#define LDSM4T(r0, r1, r2, r3, addr) \
    asm volatile("ldmatrix.sync.aligned.m8n8.x4.trans.shared.b16 {%0,%1,%2,%3}, [%4];" \
                 : "=r"(r0), "=r"(r1), "=r"(r2), "=r"(r3) : "r"(addr))

#define MMA16816(c, a0, a1, a2, a3, b0, b1) \
    asm volatile("mma.sync.aligned.m16n8k16.row.col.f32.bf16.bf16.f32 " \
                 "{%0,%1,%2,%3}, {%4,%5,%6,%7}, {%8,%9}, {%0,%1,%2,%3};" \
                 : "+f"((c)[0]), "+f"((c)[1]), "+f"((c)[2]), "+f"((c)[3]) \
                 : "r"(a0), "r"(a1), "r"(a2), "r"(a3), "r"(b0), "r"(b1))

__device__ int   g_starts[NB + 1];
__device__ float g_Q[NC * D];
__device__ float g_QtT[D * NC];   // [e][c] (fallback)
__device__ float g_QtC[NC * D];   // [c][e] (bf16 conversion source)
__device__ float g_cK[NC];
__device__ float g_P[NB * NC * D];
__device__ float g_sumA[NB * NC];
__device__ float g_H[NB * NC * D];

__device__ __forceinline__ u32 s2u(const void* p) {
    u32 a;
    asm("{ .reg .u64 t; cvta.to.shared.u64 t, %1; cvt.u32.u64 %0, t; }" : "=r"(a) : "l"(p));
    return a;
}

__device__ __forceinline__ void split2(float v0, float v1, u32& hi, u32& lo) {
    CVTBF2(hi, v0, v1);
    float h0 = __uint_as_float(hi << 16);
    float h1 = __uint_as_float(hi & 0xffff0000u);
    CVTBF2(lo, v0 - h0, v1 - h1);
}

// ---------------- meta ----------------
__global__ void k_meta(const void* __restrict__ batch, int n) {
    __shared__ int sh_is32;
    int t = threadIdx.x;
    if (t == 0) {
        long long v = ((const long long*)batch)[n / 4];
        sh_is32 = (v < 0 || v >= NB) ? 1 : 0;
    }
    __syncthreads();
    int is32 = sh_is32;
    int lo = 0, hi = n;
    while (lo < hi) {
        int mid = (lo + hi) >> 1;
        long long bv = is32 ? (long long)((const int*)batch)[mid]
                            : ((const long long*)batch)[mid];
        if (bv < (long long)t) lo = mid + 1; else hi = mid;
    }
    g_starts[t] = lo;
    if (t == 0) g_starts[NB] = n;
}

// ---------------- Q = Qp @ WQ^T + bQ ----------------
__global__ void k_q(const float* __restrict__ Qp, const float* __restrict__ Wq,
                    const float* __restrict__ bq) {
    int c = blockIdx.x, d = threadIdx.x;
    __shared__ float qp[D];
    qp[d] = Qp[c * D + d];
    __syncthreads();
    float a0 = 0.f, a1 = 0.f, a2 = 0.f, a3 = 0.f;
    #pragma unroll 4
    for (int e = 0; e < D; e += 4) {
        a0 = fmaf(qp[e + 0], Wq[d * D + e + 0], a0);
        a1 = fmaf(qp[e + 1], Wq[d * D + e + 1], a1);
        a2 = fmaf(qp[e + 2], Wq[d * D + e + 2], a2);
        a3 = fmaf(qp[e + 3], Wq[d * D + e + 3], a3);
    }
    g_Q[c * D + d] = ((a0 + a1) + (a2 + a3)) + bq[d];
}

// ---------------- Qt[c][e]; cK[c] ----------------
__global__ void k_qt(const float* __restrict__ Wk, const float* __restrict__ bk) {
    int c = blockIdx.x, e = threadIdx.x;
    __shared__ float q[D];
    q[e] = g_Q[c * D + e];
    __syncthreads();
    float a0 = 0.f, a1 = 0.f;
    #pragma unroll 4
    for (int d = 0; d < D; d += 2) {
        a0 = fmaf(q[d + 0], Wk[(d + 0) * D + e], a0);
        a1 = fmaf(q[d + 1], Wk[(d + 1) * D + e], a1);
    }
    float v = a0 + a1;
    g_QtT[e * NC + c] = v;
    g_QtC[c * D + e] = v;
    if (e == 0) {
        float ck = 0.f;
        for (int d = 0; d < D; d++) ck += q[d] * bk[d];
        g_cK[c] = ck;
    }
}

// ---------------- main fused kernel ----------------
// smem floats:
//   XnbfH [0,8192)      bf16-hi x [64n][256e], rows 512B, swz off^((n&7)<<4)
//   XnbfL [8192,16384)
//   QtbfH [16384,24576) bf16-hi Qt [64c][256e], rows 512B
//   QtbfL [24576,32768)
//   As    [32768,36864) f32 pair-swizzled [n][c]: n*64 + 2*((c>>1)^(n&31)) + (c&1)
//   AbfH  [36864,38912) bf16-hi A [64c][64n], rows 128B, SW128
//   AbfL  [38912,40960)
//   cKs 40960, sAcc 41024, flags 41088 (int cnt + 64 entries)
#define SMEM_FLOATS 41216
extern __shared__ float smem[];

__global__ __launch_bounds__(NT, 1) void k_main(const float* __restrict__ x,
                                                float* __restrict__ argout, int has_arg) {
    float* As   = smem + 32768;
    float* cKs  = smem + 40960;
    float* sAcc = smem + 41024;
    int*   flagn = (int*)(smem + 41088);
    int*   flagl = (int*)(smem + 41089);

    int t = threadIdx.x;
    int g = blockIdx.x / SPG, sl = blockIdx.x % SPG;
    int s0 = g_starts[g], s1 = g_starts[g + 1];
    int cnt = s1 - s0;
    int chunk = (cnt + SPG - 1) / SPG;
    int i0 = s0 + sl * chunk;
    int i1 = min(i0 + chunk, s1);
    if (i0 >= i1) return;  // uniform across block

    u32 sb = s2u(smem);
    const u32 xnH = sb, xnL = sb + 32768;
    const u32 qtH = sb + 65536, qtL = sb + 98304;
    const u32 abH = sb + 147456, abL = sb + 155648;

    // init: zero Xnbf, load cK, convert Qt -> split bf16 [c][e]
    for (int r = t; r < 16384; r += NT) ((u32*)smem)[r] = 0u;
    if (t < NC) { cKs[t] = g_cK[t]; sAcc[t] = 0.f; }
    if (t == 0) *flagn = 0;
    for (int r = t; r < NC * (D / 4); r += NT) {
        int c = r >> 6, e4 = r & 63;
        float4 v = *(const float4*)(g_QtC + c * D + 4 * e4);
        u32 h0, l0, h1, l1;
        split2(v.x, v.y, h0, l0);
        split2(v.z, v.w, h1, l1);
        u32 off = c * 512 + ((e4 * 8) ^ ((c & 7) << 4));
        *(uint2*)((char*)smem + (qtH - sb) + off) = make_uint2(h0, h1);
        *(uint2*)((char*)smem + (qtL - sb) + off) = make_uint2(l0, l1);
    }

    const int lane = t & 31;
    const int w    = t >> 5;            // 0..15

    // Phase-B MMA mapping: cw = c-block(16), nw = n-block(16)
    const int cw = w & 3, nw = w >> 2;
    const int pb_arow = 16 * cw + (lane & 7) + 8 * ((lane >> 3) & 1);
    const int pb_ae   = (lane >> 4) & 1;
    const int pb_asw  = (pb_arow & 7) << 4;
    const int pb_brow = 16 * nw + (lane & 7) + 8 * ((lane >> 4) & 1);
    const int pb_be   = (lane >> 3) & 1;
    const int pb_bsw  = (pb_brow & 7) << 4;
    const int wo_c = 16 * cw + (lane >> 2);
    const int wo_n = 16 * nw + 2 * (lane & 3);

    // Phase-D mapping: wr = c-block(16), wc = d-block(64)
    const int wr = w & 3, wc = w >> 2;
    const int a_row = 16 * wr + (lane & 7) + 8 * ((lane >> 3) & 1);
    const int a_hi = lane >> 4;
    const int a_sw = a_row & 7;
    const int pd_ksub = (lane & 7) + 8 * ((lane >> 3) & 1);
    const int pd_dh = (lane >> 4) & 1;

    float acc[8][4];
    #pragma unroll
    for (int nj = 0; nj < 8; nj++)
        #pragma unroll
        for (int q = 0; q < 4; q++) acc[nj][q] = 0.f;

    __syncthreads();

    for (int i = i0; i < i1; i += TILE) {
        int nb = min(TILE, i1 - i);

        // ---- stage: x -> split bf16 Xnbf [n][e] ----
        if (t == 0) *flagn = 0;
        for (int r = t; r < nb * 64; r += NT) {
            int n = r >> 6, e4 = r & 63;
            float4 v = *(const float4*)(x + (size_t)(i + n) * D + 4 * e4);
            u32 h0, l0, h1, l1;
            split2(v.x, v.y, h0, l0);
            split2(v.z, v.w, h1, l1);
            u32 off = n * 512 + ((e4 * 8) ^ ((n & 7) << 4));
            *(uint2*)((char*)smem + off)         = make_uint2(h0, h1);
            *(uint2*)((char*)smem + 32768 + off) = make_uint2(l0, l1);
        }
        __syncthreads();

        // ---- Phase B (tensor): S[16c x 16n] per warp, k = 256 ----
        {
            float sc[2][4];
            #pragma unroll
            for (int h = 0; h < 2; h++)
                #pragma unroll
                for (int q = 0; q < 4; q++) sc[h][q] = 0.f;
            #pragma unroll
            for (int ks = 0; ks < 16; ks++) {
                u32 aoff = pb_arow * 512 + ((32 * ks + 16 * pb_ae) ^ pb_asw);
                u32 boff = pb_brow * 512 + ((32 * ks + 16 * pb_be) ^ pb_bsw);
                u32 ah0, ah1, ah2, ah3, al0, al1, al2, al3;
                u32 bh0, bh1, bh2, bh3, bl0, bl1, bl2, bl3;
                LDSM4(ah0, ah1, ah2, ah3, qtH + aoff);
                LDSM4(al0, al1, al2, al3, qtL + aoff);
                LDSM4(bh0, bh1, bh2, bh3, xnH + boff);
                LDSM4(bl0, bl1, bl2, bl3, xnL + boff);
                MMA16816(sc[0], ah0, ah1, ah2, ah3, bh0, bh1);
                MMA16816(sc[0], al0, al1, al2, al3, bh0, bh1);
                MMA16816(sc[0], ah0, ah1, ah2, ah3, bl0, bl1);
                MMA16816(sc[1], ah0, ah1, ah2, ah3, bh2, bh3);
                MMA16816(sc[1], al0, al1, al2, al3, bh2, bh3);
                MMA16816(sc[1], ah0, ah1, ah2, ah3, bl2, bl3);
            }
            float ck0 = cKs[wo_c], ck1 = cKs[wo_c + 8];
            #pragma unroll
            for (int h = 0; h < 2; h++) {
                int n0 = wo_n + 8 * h;
                int m0 = n0 & 31, m1 = (n0 + 1) & 31;
                As[n0 * 64 + 2 * ((wo_c >> 1) ^ m0) + (wo_c & 1)] = sc[h][0] + ck0;
                As[(n0 + 1) * 64 + 2 * ((wo_c >> 1) ^ m1) + (wo_c & 1)] = sc[h][1] + ck0;
                int c1 = wo_c + 8;
                As[n0 * 64 + 2 * ((c1 >> 1) ^ m0) + (c1 & 1)] = sc[h][2] + ck1;
                As[(n0 + 1) * 64 + 2 * ((c1 >> 1) ^ m1) + (c1 & 1)] = sc[h][3] + ck1;
            }
        }
        __syncthreads();

        // ---- Phase C: softmax + argmax + near-tie flagging ----
        #pragma unroll
        for (int r = 0; r < TILE / 16; r++) {
            int node = r * 16 + w;
            if (node < nb) {
                int m = node & 31;
                int off0 = node * NC + 2 * ((lane >> 1) ^ m) + (lane & 1);
                int off1 = node * NC + 2 * (((lane >> 1) + 16) ^ m) + (lane & 1);
                float s0v = As[off0], s1v = As[off1];
                float p0 = s0v * 0.0625f, p1 = s1v * 0.0625f;
                float mx = fmaxf(p0, p1);
                #pragma unroll
                for (int off = 16; off; off >>= 1)
                    mx = fmaxf(mx, __shfl_xor_sync(0xffffffffu, mx, off));
                float e0 = expf(p0 - mx), e1 = expf(p1 - mx);
                float z = e0 + e1;
                #pragma unroll
                for (int off = 16; off; off >>= 1)
                    z += __shfl_xor_sync(0xffffffffu, z, off);
                float av0 = e0 / z, av1 = e1 / z;
                float bv; int bi;
                if (av0 >= av1) { bv = av0; bi = lane; } else { bv = av1; bi = lane + 32; }
                #pragma unroll
                for (int off = 16; off; off >>= 1) {
                    float ov = __shfl_xor_sync(0xffffffffu, bv, off);
                    int   oi = __shfl_xor_sync(0xffffffffu, bi, off);
                    if (ov > bv || (ov == bv && oi < bi)) { bv = ov; bi = oi; }
                }
                As[off0] = av0;
                As[off1] = av1;
                float x0 = (bi == lane) ? -1e30f : av0;
                float x1 = (bi == lane + 32) ? -1e30f : av1;
                float m2 = fmaxf(x0, x1);
                #pragma unroll
                for (int off = 16; off; off >>= 1)
                    m2 = fmaxf(m2, __shfl_xor_sync(0xffffffffu, m2, off));
                if (lane == 0) {
                    if (has_arg) {
                        int pos = (i + node) - s0;
                        argout[(size_t)g * MAXN + pos] = (float)bi;
                    }
                    if (bv - m2 < FLAG_EPS) {
                        int k = atomicAdd(flagn, 1);
                        flagl[k] = node;
                    }
                }
            }
        }
        __syncthreads();

        // ---- fallback: exact argmax for flagged nodes (rare) ----
        int nf = *flagn;
        if (has_arg) {
            for (int f = w; f < nf; f += 16) {
                int node = flagl[f];
                const float* xr = x + (size_t)(i + node) * D;
                float fs0 = 0.f, fs1 = 0.f;
                for (int e = 0; e < D; e++) {
                    float xe = __ldg(xr + e);
                    float2 q = *(const float2*)(g_QtT + e * NC + 2 * lane);
                    fs0 = fmaf(xe, q.x, fs0);
                    fs1 = fmaf(xe, q.y, fs1);
                }
                fs0 += cKs[2 * lane];
                fs1 += cKs[2 * lane + 1];
                float p0 = fs0 * 0.0625f, p1 = fs1 * 0.0625f;
                float mx = fmaxf(p0, p1);
                #pragma unroll
                for (int off = 16; off; off >>= 1)
                    mx = fmaxf(mx, __shfl_xor_sync(0xffffffffu, mx, off));
                float e0 = expf(p0 - mx), e1 = expf(p1 - mx);
                float z = e0 + e1;
                #pragma unroll
                for (int off = 16; off; off >>= 1)
                    z += __shfl_xor_sync(0xffffffffu, z, off);
                float av0 = e0 / z, av1 = e1 / z;
                float bv; int bi;
                if (av0 >= av1) { bv = av0; bi = 2 * lane; } else { bv = av1; bi = 2 * lane + 1; }
                #pragma unroll
                for (int off = 16; off; off >>= 1) {
                    float ov = __shfl_xor_sync(0xffffffffu, bv, off);
                    int   oi = __shfl_xor_sync(0xffffffffu, bi, off);
                    if (ov > bv || (ov == bv && oi < bi)) { bv = ov; bi = oi; }
                }
                if (lane == 0) {
                    int pos = (i + node) - s0;
                    argout[(size_t)g * MAXN + pos] = (float)bi;
                }
            }
        }

        // sumA accumulation (threads < 64)
        if (t < NC) {
            float sa = sAcc[t];
            int gidx = t >> 1, par = t & 1;
            for (int n = 0; n < nb; n++)
                sa += As[n * NC + 2 * (gidx ^ (n & 31)) + par];
            sAcc[t] = sa;
        }

        // ---- convert A -> AbfH/AbfL ([c][n], rows 128B SW128) ----
        {
            int c = t >> 3, n0 = (t & 7) * 8;
            u32 ph[4], pl[4];
            #pragma unroll
            for (int q = 0; q < 4; q++) {
                int na = n0 + 2 * q, nb2 = na + 1;
                float va = (na < nb)  ? As[na * NC + 2 * ((c >> 1) ^ (na & 31)) + (c & 1)] : 0.f;
                float vb = (nb2 < nb) ? As[nb2 * NC + 2 * ((c >> 1) ^ (nb2 & 31)) + (c & 1)] : 0.f;
                split2(va, vb, ph[q], pl[q]);
            }
            u32 so = (c * 128 + n0 * 2);
            so = so ^ ((so >> 3) & 0x70);
            *(uint4*)((char*)smem + (abH - sb) + so) = make_uint4(ph[0], ph[1], ph[2], ph[3]);
            *(uint4*)((char*)smem + (abL - sb) + so) = make_uint4(pl[0], pl[1], pl[2], pl[3]);
        }
        __syncthreads();

        // ---- Phase D (tensor): acc += A[c][n] * X[n][d] via ldmatrix.trans ----
        #pragma unroll
        for (int ks = 0; ks < 4; ks++) {
            u32 a_off = (a_row << 7) + (((2 * ks + a_hi) ^ a_sw) << 4);
            u32 ah0, ah1, ah2, ah3, al0, al1, al2, al3;
            LDSM4(ah0, ah1, ah2, ah3, abH + a_off);
            LDSM4(al0, al1, al2, al3, abL + a_off);
            int k_row = 16 * ks + pd_ksub;
            u32 bbase = k_row * 512;
            u32 bsw = (k_row & 7) << 4;
            #pragma unroll
            for (int jj = 0; jj < 4; jj++) {
                u32 b_off = bbase + ((128 * wc + 32 * jj + 16 * pd_dh) ^ bsw);
                u32 bh0, bh1, bh2, bh3, bl0, bl1, bl2, bl3;
                LDSM4T(bh0, bh1, bh2, bh3, xnH + b_off);
                LDSM4T(bl0, bl1, bl2, bl3, xnL + b_off);
                MMA16816(acc[2 * jj],     ah0, ah1, ah2, ah3, bh0, bh1);
                MMA16816(acc[2 * jj],     al0, al1, al2, al3, bh0, bh1);
                MMA16816(acc[2 * jj],     ah0, ah1, ah2, ah3, bl0, bl1);
                MMA16816(acc[2 * jj + 1], ah0, ah1, ah2, ah3, bh2, bh3);
                MMA16816(acc[2 * jj + 1], al0, al1, al2, al3, bh2, bh3);
                MMA16816(acc[2 * jj + 1], ah0, ah1, ah2, ah3, bl2, bl3);
            }
        }
        __syncthreads();
    }

    // ---- flush accumulators ----
    {
        float* pgb = g_P + (size_t)g * NC * D;
        int r0 = 16 * wr + (lane >> 2);
        #pragma unroll
        for (int nj = 0; nj < 8; nj++) {
            int col = 64 * wc + 8 * nj + 2 * (lane & 3);
            atomicAdd(pgb + (size_t)r0 * D + col,           acc[nj][0]);
            atomicAdd(pgb + (size_t)r0 * D + col + 1,       acc[nj][1]);
            atomicAdd(pgb + (size_t)(r0 + 8) * D + col,     acc[nj][2]);
            atomicAdd(pgb + (size_t)(r0 + 8) * D + col + 1, acc[nj][3]);
        }
    }
    if (t < NC) atomicAdd(&g_sumA[g * NC + t], sAcc[t]);
}

// ---------------- epilogue GEMMs v2: register-tiled f32x2 ----------------
// Block: 32 rows x 256 cols, 256 threads. Thread (tx 0..127, ty 0..1):
// cols {2tx, 2tx+1}, rows [16ty, 16ty+16) as 8 f32x2 row-pairs.
// Ash transposed [k][row], stride 34 (STS conflict <=2-way, LDS.64 8B-aligned,
// row-pair reads warp-uniform broadcast).
#define ASTR 34
template <int MODE>
__global__ __launch_bounds__(256) void k_gemm(const float* __restrict__ Bmat,
                                              const float* __restrict__ bias,
                                              float* __restrict__ Cout) {
    __shared__ float Ash[D * ASTR];
    int t = threadIdx.x;
    int tx = t & 127, ty = t >> 7;
    int r0 = blockIdx.x * 32;
    const float* Amat = (MODE == 0) ? g_P : g_H;

    {   // stage A [32r][256k] -> Ash[k][r] (coalesced LDG.128, scatter STS)
        int row = t >> 3, k4 = (t & 7) * 4;
        const float* src = Amat + (size_t)(r0 + row) * D + k4;
        #pragma unroll
        for (int it = 0; it < 8; it++) {
            float4 v = *(const float4*)(src + 32 * it);
            int kb = k4 + 32 * it;
            Ash[(kb + 0) * ASTR + row] = v.x;
            Ash[(kb + 1) * ASTR + row] = v.y;
            Ash[(kb + 2) * ASTR + row] = v.z;
            Ash[(kb + 3) * ASTR + row] = v.w;
        }
    }
    __syncthreads();

    int q0 = 2 * tx;
    int rbase = 16 * ty;
    ull acc2[8][2];
    #pragma unroll
    for (int p = 0; p < 8; p++) { acc2[p][0] = 0ull; acc2[p][1] = 0ull; }

    const float* b0p = Bmat + (size_t)q0 * D;
    const float* b1p = Bmat + (size_t)(q0 + 1) * D;
    for (int k = 0; k < D; k += 4) {
        float4 bv0 = *(const float4*)(b0p + k);
        float4 bv1 = *(const float4*)(b1p + k);
        float b0s[4] = {bv0.x, bv0.y, bv0.z, bv0.w};
        float b1s[4] = {bv1.x, bv1.y, bv1.z, bv1.w};
        #pragma unroll
        for (int kk = 0; kk < 4; kk++) {
            ull bd0, bd1;
            DUP(bd0, b0s[kk]);
            DUP(bd1, b1s[kk]);
            const ull* ar = (const ull*)(Ash + (k + kk) * ASTR + rbase);
            #pragma unroll
            for (int p = 0; p < 8; p++) {
                ull av = ar[p];
                FMA2(acc2[p][0], av, bd0);
                FMA2(acc2[p][1], av, bd1);
            }
        }
    }

    float bias0 = bias[q0], bias1 = bias[q0 + 1];
    #pragma unroll
    for (int p = 0; p < 8; p++) {
        int r = r0 + rbase + 2 * p;
        float v00 = __uint_as_float((u32)(acc2[p][0] & 0xffffffffull));
        float v01 = __uint_as_float((u32)(acc2[p][1] & 0xffffffffull));
        float v10 = __uint_as_float((u32)(acc2[p][0] >> 32));
        float v11 = __uint_as_float((u32)(acc2[p][1] >> 32));
        if (MODE == 0) {
            int c0 = r & (NC - 1), c1 = (r + 1) & (NC - 1);
            float sa0 = g_sumA[r], sa1 = g_sumA[r + 1];
            v00 += g_Q[c0 * D + q0]     + sa0 * bias0;
            v01 += g_Q[c0 * D + q0 + 1] + sa0 * bias1;
            v10 += g_Q[c1 * D + q0]     + sa1 * bias0;
            v11 += g_Q[c1 * D + q0 + 1] + sa1 * bias1;
            *(float2*)(g_H + (size_t)r * D + q0)       = make_float2(v00, v01);
            *(float2*)(g_H + (size_t)(r + 1) * D + q0) = make_float2(v10, v11);
        } else {
            v00 = fmaxf(v00 + bias0, 0.f);
            v01 = fmaxf(v01 + bias1, 0.f);
            v10 = fmaxf(v10 + bias0, 0.f);
            v11 = fmaxf(v11 + bias1, 0.f);
            *(float2*)(Cout + (size_t)r * D + q0)       = make_float2(v00, v01);
            *(float2*)(Cout + (size_t)(r + 1) * D + q0) = make_float2(v10, v11);
        }
    }
}

// ---------------- mask output ----------------
__global__ void k_mask(float* __restrict__ maskout) {
    int idx = blockIdx.x * blockDim.x + threadIdx.x;
    if (idx >= NB * MAXN) return;
    int b = idx >> 12, pos = idx & (MAXN - 1);
    int cnt = g_starts[b + 1] - g_starts[b];
    maskout[idx] = (pos < cnt) ? 1.f : 0.f;
}

extern "C" void kernel_launch(void* const* d_in, const int* in_sizes, int n_in,
                              void* d_out, int out_size) {
    const float* x    = (const float*)d_in[0];
    const void*  bat  = d_in[1];
    const float* Qp   = (const float*)d_in[2];
    const float* WQ_w = (const float*)d_in[3];
    const float* WQ_b = (const float*)d_in[4];
    const float* WK_w = (const float*)d_in[5];
    const float* WK_b = (const float*)d_in[6];
    const float* WV_w = (const float*)d_in[7];
    const float* WV_b = (const float*)d_in[8];
    const float* WO_w = (const float*)d_in[9];
    const float* WO_b = (const float*)d_in[10];
    (void)n_in;

    int n_nodes = in_sizes[0] / D;
    float* out = (float*)d_out;
    int has_arg  = out_size >= (NB * NC * D + NB * MAXN);
    int has_mask = out_size >= (NB * NC * D + 2 * NB * MAXN);
    float* argout  = out + NB * NC * D;
    float* maskout = argout + NB * MAXN;

    void *pP = nullptr, *pS = nullptr;
    cudaGetSymbolAddress(&pP, g_P);
    cudaGetSymbolAddress(&pS, g_sumA);
    cudaMemsetAsync(pP, 0, sizeof(float) * NB * NC * D, 0);
    cudaMemsetAsync(pS, 0, sizeof(float) * NB * NC, 0);
    if (has_arg) cudaMemsetAsync(argout, 0, sizeof(float) * NB * MAXN, 0);

    k_meta<<<1, NB>>>(bat, n_nodes);
    k_q<<<NC, 256>>>(Qp, WQ_w, WQ_b);
    k_qt<<<NC, 256>>>(WK_w, WK_b);

    const int smem_main = SMEM_FLOATS * (int)sizeof(float);
    cudaFuncSetAttribute(k_main, cudaFuncAttributeMaxDynamicSharedMemorySize, smem_main);
    k_main<<<NB * SPG, NT, smem_main>>>(x, argout, has_arg);

    k_gemm<0><<<(NB * NC) / 32, 256>>>(WV_w, WV_b, nullptr);
    k_gemm<1><<<(NB * NC) / 32, 256>>>(WO_w, WO_b, out);

    if (has_mask) k_mask<<<(NB * MAXN) / 256, 256>>>(maskout);
}